// round 10
// baseline (speedup 1.0000x reference)
#include <cuda_runtime.h>
#include <math.h>

#define B_ 2
#define S_ 1024
#define D_ 768
#define H_ 12
#define E_ 8
#define DH_ 64
#define DFF_ 2048
#define NTOK (B_*S_)
#define CAP_ 320
#define NOUT (NTOK*D_)

// ---------------- scratch (device globals; no allocation allowed) -------------
__device__ float g_xln [NTOK*D_];
__device__ float g_q   [NTOK*D_];
__device__ float g_k   [NTOK*D_];
__device__ float g_vsel[NTOK*D_];
__device__ float g_attn[NTOK*D_];
__device__ float g_x1  [NTOK*D_];
__device__ float g_xln2[NTOK*D_];
__device__ float g_rlog[NTOK*(H_*E_)];
__device__ int   g_eidx[NTOK*H_];
__device__ int   g_hard[H_*E_];
__device__ float g_m[B_*H_*S_];
__device__ float g_l[B_*H_*S_];
__device__ int   g_tk_idx[NTOK*2];
__device__ float g_tk_prob[NTOK*2];
__device__ int   g_token_slot[NTOK*2];
__device__ int   g_slot_token[E_*CAP_];
__device__ float g_slot_w[E_*CAP_];
__device__ int   g_ecount[E_];
__device__ float g_hbuf[E_*CAP_*DFF_];
__device__ float g_sout[E_*CAP_*D_];

// ---------------- tf32 tensor-core helpers -------------------------------------
__device__ __forceinline__ unsigned to_tf32(float f) {
    unsigned u; asm("cvt.rna.tf32.f32 %0,%1;" : "=r"(u) : "f"(f)); return u;
}
__device__ __forceinline__ void mma_tf32(float c[4], const unsigned a[4], const unsigned b[2]) {
    asm("mma.sync.aligned.m16n8k8.row.col.f32.tf32.tf32.f32 "
        "{%0,%1,%2,%3},{%4,%5,%6,%7},{%8,%9},{%0,%1,%2,%3};"
        : "+f"(c[0]), "+f"(c[1]), "+f"(c[2]), "+f"(c[3])
        : "r"(a[0]), "r"(a[1]), "r"(a[2]), "r"(a[3]), "r"(b[0]), "r"(b[1]));
}

// ---------------- LayerNorm (warp per row, float4); optional g_hard clear ------
__global__ void ln_kernel(const float* __restrict__ x, const float* __restrict__ g,
                          const float* __restrict__ b, float* __restrict__ out,
                          int clear_hard) {
    if (clear_hard && blockIdx.x == 0 && threadIdx.x < H_ * E_) g_hard[threadIdx.x] = 0;
    int wid = threadIdx.x >> 5, lane = threadIdx.x & 31;
    int row = blockIdx.x * 8 + wid;
    const float4* xr = (const float4*)(x + (size_t)row * D_);
    float4 v[6];
    float s = 0.f, s2 = 0.f;
#pragma unroll
    for (int i = 0; i < 6; i++) {
        v[i] = xr[lane + i * 32];
        s  += v[i].x + v[i].y + v[i].z + v[i].w;
        s2 += v[i].x * v[i].x + v[i].y * v[i].y + v[i].z * v[i].z + v[i].w * v[i].w;
    }
#pragma unroll
    for (int o = 16; o > 0; o >>= 1) {
        s  += __shfl_xor_sync(0xffffffffu, s,  o);
        s2 += __shfl_xor_sync(0xffffffffu, s2, o);
    }
    float mean = s * (1.f / D_);
    float inv  = rsqrtf(s2 * (1.f / D_) - mean * mean + 1e-5f);
    float4* orow = (float4*)(out + (size_t)row * D_);
    const float4* g4 = (const float4*)g;
    const float4* b4 = (const float4*)b;
#pragma unroll
    for (int i = 0; i < 6; i++) {
        float4 gg = g4[lane + i * 32], bb = b4[lane + i * 32];
        float4 o;
        o.x = (v[i].x - mean) * inv * gg.x + bb.x;
        o.y = (v[i].y - mean) * inv * gg.y + bb.y;
        o.z = (v[i].z - mean) * inv * gg.z + bb.z;
        o.w = (v[i].w - mean) * inv * gg.w + bb.w;
        orow[lane + i * 32] = o;
    }
}

// ---------------- LN2 + FFN gate fused (warp per row) --------------------------
__global__ void ln_gate_kernel(const float* __restrict__ x, const float* __restrict__ g,
                               const float* __restrict__ b, const float* __restrict__ gff,
                               float* __restrict__ out) {
    int wid = threadIdx.x >> 5, lane = threadIdx.x & 31;
    int row = blockIdx.x * 8 + wid;
    const float4* xr = (const float4*)(x + (size_t)row * D_);
    float4 v[6];
    float s = 0.f, s2 = 0.f;
#pragma unroll
    for (int i = 0; i < 6; i++) {
        v[i] = xr[lane + i * 32];
        s  += v[i].x + v[i].y + v[i].z + v[i].w;
        s2 += v[i].x * v[i].x + v[i].y * v[i].y + v[i].z * v[i].z + v[i].w * v[i].w;
    }
#pragma unroll
    for (int o = 16; o > 0; o >>= 1) {
        s  += __shfl_xor_sync(0xffffffffu, s,  o);
        s2 += __shfl_xor_sync(0xffffffffu, s2, o);
    }
    float mean = s * (1.f / D_);
    float inv  = rsqrtf(s2 * (1.f / D_) - mean * mean + 1e-5f);
    float4* orow = (float4*)(out + (size_t)row * D_);
    const float4* g4 = (const float4*)g;
    const float4* b4 = (const float4*)b;
    float acc[8] = {};
#pragma unroll
    for (int i = 0; i < 6; i++) {
        int c = lane + i * 32;
        float4 gg = g4[c], bb = b4[c];
        float4 o;
        o.x = (v[i].x - mean) * inv * gg.x + bb.x;
        o.y = (v[i].y - mean) * inv * gg.y + bb.y;
        o.z = (v[i].z - mean) * inv * gg.z + bb.z;
        o.w = (v[i].w - mean) * inv * gg.w + bb.w;
        orow[c] = o;
        int dbase = c * 4;
        float ov[4] = { o.x, o.y, o.z, o.w };
#pragma unroll
        for (int j = 0; j < 4; j++) {
            float xv = ov[j];
            float4 gA = *(const float4*)(gff + (size_t)(dbase + j) * E_);
            float4 gB = *(const float4*)(gff + (size_t)(dbase + j) * E_ + 4);
            acc[0] += xv * gA.x; acc[1] += xv * gA.y; acc[2] += xv * gA.z; acc[3] += xv * gA.w;
            acc[4] += xv * gB.x; acc[5] += xv * gB.y; acc[6] += xv * gB.z; acc[7] += xv * gB.w;
        }
    }
#pragma unroll
    for (int off = 16; off > 0; off >>= 1)
#pragma unroll
        for (int i = 0; i < 8; i++)
            acc[i] += __shfl_xor_sync(0xffffffffu, acc[i], off);
    if (lane == 0) {
        int i0 = 0; float v0 = acc[0];
#pragma unroll
        for (int e = 1; e < E_; e++) if (acc[e] > v0) { v0 = acc[e]; i0 = e; }
        int i1 = -1; float v1 = -3.4e38f;
#pragma unroll
        for (int e = 0; e < E_; e++) { if (e == i0) continue; if (acc[e] > v1) { v1 = acc[e]; i1 = e; } }
        float e1 = expf(v1 - v0);
        float z = 1.f + e1;
        g_tk_idx[row * 2] = i0; g_tk_idx[row * 2 + 1] = i1;
        g_tk_prob[row * 2] = 1.f / z; g_tk_prob[row * 2 + 1] = e1 / z;
    }
}

// ---------------- tf32 tensor-core GEMM, 128x64x16 tiles, double buffered ------
// MODE 0: fused QKR. bx<12: Wq->g_q | bx<24: Wk->g_k | bx>=24: Wr->g_rlog (N=96)
// MODE 1: FFN GEMM1 (gathered A rows, ReLU). z=e. B=W1[e]. C=g_hbuf[e].
// MODE 2: FFN GEMM2 (slot-weight scale).     z=e. B=W2[e]. C=g_sout[e].
#define ASTRIDE 20
#define BSTRIDE 72
template<int MODE>
__global__ __launch_bounds__(256)
void gemm_tf32(const float* __restrict__ P0, const float* __restrict__ P1,
               const float* __restrict__ P2) {
    __shared__ __align__(16) unsigned As[2][128 * ASTRIDE];
    __shared__ __align__(16) unsigned Bs[2][16 * BSTRIDE];

    const int tid = threadIdx.x, wid = tid >> 5, lane = tid & 31;
    const int e  = blockIdx.z;
    const int m0 = blockIdx.y * 128;

    int N, K, count, n0;
    const float* Bm;
    float* C;
    const float* Abase;
    if (MODE == 0) {
        K = D_; count = NTOK; Abase = g_xln;
        int bx = blockIdx.x;
        if (bx < 12)      { Bm = P0; C = g_q;    N = D_; n0 = bx * 64; }
        else if (bx < 24) { Bm = P1; C = g_k;    N = D_; n0 = (bx - 12) * 64; }
        else              { Bm = P2; C = g_rlog; N = 96; n0 = (bx - 24) * 64; }
    } else if (MODE == 1) {
        N = DFF_; K = D_; count = g_ecount[e]; n0 = blockIdx.x * 64;
        if (count <= 0 || m0 >= count) return;
        Bm = P0 + (size_t)e * D_ * DFF_;
        C  = g_hbuf + (size_t)e * CAP_ * DFF_;
        Abase = g_xln2;
    } else {
        N = D_; K = DFF_; count = g_ecount[e]; n0 = blockIdx.x * 64;
        if (count <= 0 || m0 >= count) return;
        Bm = P0 + (size_t)e * DFF_ * D_;
        C  = g_sout + (size_t)e * CAP_ * D_;
        Abase = g_hbuf + (size_t)e * CAP_ * DFF_;
    }

    const int sm_r = tid >> 1;
    const int sm_k = (tid & 1) * 8;
    const int brow = tid >> 4;
    const int bcol = (tid & 15) * 4;

    const float* Aptr;
    {
        int r = m0 + sm_r;
        if (r >= count) r = count - 1;
        if (MODE == 1)
            Aptr = Abase + (size_t)g_slot_token[e * CAP_ + r] * D_ + sm_k;
        else
            Aptr = Abase + (size_t)r * K + sm_k;
    }
    int bc_eff = bcol;
    if (n0 + bcol + 4 > N) bc_eff = N - 4 - n0;
    const float* Bptr = Bm + (size_t)brow * N + n0 + bc_eff;

    const int wm0 = (wid & 3) * 32;
    const int wn0 = (wid >> 2) * 32;
    const int gr = lane >> 2, gc = lane & 3;

    float acc[2][4][4];
#pragma unroll
    for (int i = 0; i < 2; i++)
#pragma unroll
        for (int j = 0; j < 4; j++)
#pragma unroll
            for (int q = 0; q < 4; q++) acc[i][j][q] = 0.f;

    const int nk = K / 16;
    float4 av0, av1, bv;

    // preload tile 0 -> buffer 0
    av0 = *(const float4*)(Aptr);
    av1 = *(const float4*)(Aptr + 4);
    bv  = *(const float4*)(Bptr);
    {
        uint4 u0 = make_uint4(to_tf32(av0.x), to_tf32(av0.y), to_tf32(av0.z), to_tf32(av0.w));
        uint4 u1 = make_uint4(to_tf32(av1.x), to_tf32(av1.y), to_tf32(av1.z), to_tf32(av1.w));
        uint4 ub = make_uint4(to_tf32(bv.x),  to_tf32(bv.y),  to_tf32(bv.z),  to_tf32(bv.w));
        *(uint4*)&As[0][sm_r * ASTRIDE + sm_k]     = u0;
        *(uint4*)&As[0][sm_r * ASTRIDE + sm_k + 4] = u1;
        *(uint4*)&Bs[0][brow * BSTRIDE + bcol]     = ub;
    }
    __syncthreads();

    for (int kb = 0; kb < nk; kb++) {
        const int buf = kb & 1;
        if (kb + 1 < nk) {
            av0 = *(const float4*)(Aptr + (kb + 1) * 16);
            av1 = *(const float4*)(Aptr + (kb + 1) * 16 + 4);
            bv  = *(const float4*)(Bptr + (size_t)(kb + 1) * 16 * N);
        }
        const unsigned* Ab = As[buf];
        const unsigned* Bb = Bs[buf];
#pragma unroll
        for (int kk = 0; kk < 16; kk += 8) {
            unsigned a[2][4];
#pragma unroll
            for (int mf = 0; mf < 2; mf++) {
                int mb = wm0 + mf * 16;
                a[mf][0] = Ab[(mb + gr)     * ASTRIDE + kk + gc];
                a[mf][1] = Ab[(mb + gr + 8) * ASTRIDE + kk + gc];
                a[mf][2] = Ab[(mb + gr)     * ASTRIDE + kk + gc + 4];
                a[mf][3] = Ab[(mb + gr + 8) * ASTRIDE + kk + gc + 4];
            }
#pragma unroll
            for (int nf = 0; nf < 4; nf++) {
                int nb = wn0 + nf * 8 + gr;
                unsigned b[2];
                b[0] = Bb[(kk + gc)     * BSTRIDE + nb];
                b[1] = Bb[(kk + gc + 4) * BSTRIDE + nb];
                mma_tf32(acc[0][nf], a[0], b);
                mma_tf32(acc[1][nf], a[1], b);
            }
        }
        if (kb + 1 < nk) {
            uint4 u0 = make_uint4(to_tf32(av0.x), to_tf32(av0.y), to_tf32(av0.z), to_tf32(av0.w));
            uint4 u1 = make_uint4(to_tf32(av1.x), to_tf32(av1.y), to_tf32(av1.z), to_tf32(av1.w));
            uint4 ub = make_uint4(to_tf32(bv.x),  to_tf32(bv.y),  to_tf32(bv.z),  to_tf32(bv.w));
            *(uint4*)&As[buf ^ 1][sm_r * ASTRIDE + sm_k]     = u0;
            *(uint4*)&As[buf ^ 1][sm_r * ASTRIDE + sm_k + 4] = u1;
            *(uint4*)&Bs[buf ^ 1][brow * BSTRIDE + bcol]     = ub;
        }
        __syncthreads();
    }

#pragma unroll
    for (int mf = 0; mf < 2; mf++) {
        int rbase = m0 + wm0 + mf * 16 + gr;
#pragma unroll
        for (int half = 0; half < 2; half++) {
            int r = rbase + half * 8;
            if (MODE != 0 && r >= count) continue;
            float w = 1.f;
            if (MODE == 2) w = g_slot_w[e * CAP_ + r];
#pragma unroll
            for (int nf = 0; nf < 4; nf++) {
                int cc = n0 + wn0 + nf * 8 + gc * 2;
                if (MODE == 0 && cc + 2 > N) continue;
                float v0 = acc[mf][nf][half * 2 + 0];
                float v1 = acc[mf][nf][half * 2 + 1];
                if (MODE == 1) { v0 = fmaxf(v0, 0.f); v1 = fmaxf(v1, 0.f); }
                else if (MODE == 2) { v0 *= w; v1 *= w; }
                *(float2*)(C + (size_t)r * N + cc) = make_float2(v0, v1);
            }
        }
    }
}

__global__ void router_argmax() {
    int idx = blockIdx.x * 256 + threadIdx.x;
    if (idx >= NTOK * H_) return;
    int row = idx / H_, h = idx - row * H_;
    const float* lg = g_rlog + (size_t)row * 96 + h * 8;
    float best = lg[0]; int bi = 0;
#pragma unroll
    for (int e = 1; e < E_; e++) { float v = lg[e]; if (v > best) { best = v; bi = e; } }
    g_eidx[row * H_ + h] = bi;
    atomicAdd(&g_hard[h * E_ + bi], 1);
}

// ---------------- per (token, head) expert matvecs ----------------------------
__global__ void vsel_kernel(const float* __restrict__ Wv) {
    int row = blockIdx.x, tid = threadIdx.x; // 384 = 12 warps
    int h = tid >> 5, lane = tid & 31;
    int e = g_eidx[row * H_ + h];
    const float* wv = Wv + (size_t)(h * E_ + e) * DH_ * DH_;
    const float* xh = g_xln + (size_t)row * D_ + h * DH_;
    float a0 = 0.f, a1 = 0.f, b0 = 0.f, b1 = 0.f;
#pragma unroll 8
    for (int d = 0; d < DH_; d += 2) {
        float x0 = xh[d], x1 = xh[d + 1];
        a0 += x0 * wv[d * DH_ + lane];
        b0 += x0 * wv[d * DH_ + lane + 32];
        a1 += x1 * wv[(d + 1) * DH_ + lane];
        b1 += x1 * wv[(d + 1) * DH_ + lane + 32];
    }
    g_vsel[(size_t)row * D_ + h * DH_ + lane]      = a0 + a1;
    g_vsel[(size_t)row * D_ + h * DH_ + lane + 32] = b0 + b1;
}

__global__ void osel_kernel(const float* __restrict__ Wo, const float* __restrict__ x) {
    int row = blockIdx.x, tid = threadIdx.x; // 384
    int h = tid >> 5, lane = tid & 31;
    int e = g_eidx[row * H_ + h];
    const float* wo = Wo + (size_t)(h * E_ + e) * DH_ * DH_;
    const float* af = g_attn + (size_t)row * D_ + h * DH_;
    float a0 = 0.f, a1 = 0.f, b0 = 0.f, b1 = 0.f;
#pragma unroll 8
    for (int f = 0; f < DH_; f += 2) {
        float v0 = af[f], v1 = af[f + 1];
        a0 += v0 * wo[f * DH_ + lane];
        b0 += v0 * wo[f * DH_ + lane + 32];
        a1 += v1 * wo[(f + 1) * DH_ + lane];
        b1 += v1 * wo[(f + 1) * DH_ + lane + 32];
    }
    size_t o0 = (size_t)row * D_ + h * DH_ + lane;
    g_x1[o0]      = x[o0]      + a0 + a1;
    g_x1[o0 + 32] = x[o0 + 32] + b0 + b1;
}

// ---------------- attention pass 1 (tf32 MMA): row stats m_s, l_s --------------
__global__ __launch_bounds__(256)
void attn_pass1() {
    extern __shared__ unsigned dsp[];
    unsigned* uQ = dsp;
    unsigned* uK = dsp + 64 * 68;
    float* Ss = (float*)(dsp + 2 * 64 * 68);
    int s0 = blockIdx.x * 64, h = blockIdx.y, b = blockIdx.z;
    int tid = threadIdx.x, wid = tid >> 5, lane = tid & 31;
    int gr = lane >> 2, gc = lane & 3;
    const float* qb = g_q + (size_t)b * S_ * D_ + h * DH_;
    const float* kb = g_k + (size_t)b * S_ * D_ + h * DH_;
    {
        int r = tid >> 2, dg = (tid & 3) * 16;
        const float* src = qb + (size_t)(s0 + r) * D_ + dg;
#pragma unroll
        for (int i = 0; i < 4; i++) {
            float4 v = *(const float4*)(src + i * 4);
            uQ[r * 68 + dg + i * 4 + 0] = to_tf32(v.x);
            uQ[r * 68 + dg + i * 4 + 1] = to_tf32(v.y);
            uQ[r * 68 + dg + i * 4 + 2] = to_tf32(v.z);
            uQ[r * 68 + dg + i * 4 + 3] = to_tf32(v.w);
        }
    }
    const int wm0 = (wid & 1) * 32, wn0 = (wid >> 1) * 16;
    const int rr = tid >> 2, qq = tid & 3;
    float run_m = -INFINITY, run_l = 0.f;

    for (int t0 = 0; t0 <= s0; t0 += 64) {
        {
            int r = tid >> 2, dg = (tid & 3) * 16;
            const float* src = kb + (size_t)(t0 + r) * D_ + dg;
#pragma unroll
            for (int i = 0; i < 4; i++) {
                float4 v = *(const float4*)(src + i * 4);
                uK[(dg + i * 4 + 0) * 68 + r] = to_tf32(v.x);
                uK[(dg + i * 4 + 1) * 68 + r] = to_tf32(v.y);
                uK[(dg + i * 4 + 2) * 68 + r] = to_tf32(v.z);
                uK[(dg + i * 4 + 3) * 68 + r] = to_tf32(v.w);
            }
        }
        __syncthreads();
        float c[2][2][4];
#pragma unroll
        for (int mf = 0; mf < 2; mf++)
#pragma unroll
            for (int nf = 0; nf < 2; nf++)
#pragma unroll
                for (int q = 0; q < 4; q++) c[mf][nf][q] = 0.f;
#pragma unroll
        for (int kk = 0; kk < 64; kk += 8) {
            unsigned a[2][4], bf[2][2];
#pragma unroll
            for (int mf = 0; mf < 2; mf++) {
                int mb = wm0 + mf * 16;
                a[mf][0] = uQ[(mb + gr)     * 68 + kk + gc];
                a[mf][1] = uQ[(mb + gr + 8) * 68 + kk + gc];
                a[mf][2] = uQ[(mb + gr)     * 68 + kk + gc + 4];
                a[mf][3] = uQ[(mb + gr + 8) * 68 + kk + gc + 4];
            }
#pragma unroll
            for (int nf = 0; nf < 2; nf++) {
                int nb = wn0 + nf * 8 + gr;
                bf[nf][0] = uK[(kk + gc)     * 68 + nb];
                bf[nf][1] = uK[(kk + gc + 4) * 68 + nb];
            }
#pragma unroll
            for (int mf = 0; mf < 2; mf++)
#pragma unroll
                for (int nf = 0; nf < 2; nf++)
                    mma_tf32(c[mf][nf], a[mf], bf[nf]);
        }
#pragma unroll
        for (int mf = 0; mf < 2; mf++)
#pragma unroll
            for (int nf = 0; nf < 2; nf++) {
                int row = wm0 + mf * 16 + gr, col = wn0 + nf * 8 + 2 * gc;
                *(float2*)&Ss[row * 72 + col]       = make_float2(c[mf][nf][0], c[mf][nf][1]);
                *(float2*)&Ss[(row + 8) * 72 + col] = make_float2(c[mf][nf][2], c[mf][nf][3]);
            }
        __syncthreads();
        float v[16];
#pragma unroll
        for (int i = 0; i < 4; i++) {
            float4 t4 = *(const float4*)&Ss[rr * 72 + qq * 16 + i * 4];
            v[i * 4 + 0] = t4.x; v[i * 4 + 1] = t4.y; v[i * 4 + 2] = t4.z; v[i * 4 + 3] = t4.w;
        }
        int gs = s0 + rr;
        float mx = -INFINITY;
#pragma unroll
        for (int cI = 0; cI < 16; cI++) {
            int gt = t0 + qq * 16 + cI;
            if (gt <= gs) mx = fmaxf(mx, v[cI] * 0.125f);
        }
        mx = fmaxf(mx, __shfl_xor_sync(0xffffffffu, mx, 1));
        mx = fmaxf(mx, __shfl_xor_sync(0xffffffffu, mx, 2));
        float mn = fmaxf(run_m, mx);
        float alpha = __expf(run_m - mn);
        float sum = 0.f;
#pragma unroll
        for (int cI = 0; cI < 16; cI++) {
            int gt = t0 + qq * 16 + cI;
            if (gt <= gs) sum += __expf(v[cI] * 0.125f - mn);
        }
        sum += __shfl_xor_sync(0xffffffffu, sum, 1);
        sum += __shfl_xor_sync(0xffffffffu, sum, 2);
        run_l = run_l * alpha + sum;
        run_m = mn;
    }
    if (qq == 0) {
        int o = (b * H_ + h) * S_ + s0 + rr;
        g_m[o] = run_m; g_l[o] = run_l;
    }
}

// ---------------- attention pass 2 (tf32 MMA): out[t] = sum_s P[s,t] v[s] ------
__global__ __launch_bounds__(256)
void attn_pass2() {
    extern __shared__ unsigned dsp2[];
    unsigned* uK = dsp2;
    unsigned* uQ = dsp2 + 4352;
    unsigned* uV = dsp2 + 8704;
    unsigned* uP = dsp2 + 13056;
    float* srm  = (float*)(dsp2 + 17664);
    float* sinv = srm + 64;
    int t0 = blockIdx.x * 64, h = blockIdx.y, b = blockIdx.z;
    int tid = threadIdx.x, wid = tid >> 5, lane = tid & 31;
    int gr = lane >> 2, gc = lane & 3;
    const float* qb = g_q    + (size_t)b * S_ * D_ + h * DH_;
    const float* kb = g_k    + (size_t)b * S_ * D_ + h * DH_;
    const float* vb = g_vsel + (size_t)b * S_ * D_ + h * DH_;
    {
        int r = tid >> 2, dg = (tid & 3) * 16;
        const float* src = kb + (size_t)(t0 + r) * D_ + dg;
#pragma unroll
        for (int i = 0; i < 4; i++) {
            float4 v = *(const float4*)(src + i * 4);
            uK[(dg + i * 4 + 0) * 68 + r] = to_tf32(v.x);
            uK[(dg + i * 4 + 1) * 68 + r] = to_tf32(v.y);
            uK[(dg + i * 4 + 2) * 68 + r] = to_tf32(v.z);
            uK[(dg + i * 4 + 3) * 68 + r] = to_tf32(v.w);
        }
    }
    const int wm0 = (wid & 1) * 32, wn0 = (wid >> 1) * 16;
    float O[2][2][4];
#pragma unroll
    for (int mf = 0; mf < 2; mf++)
#pragma unroll
        for (int nf = 0; nf < 2; nf++)
#pragma unroll
            for (int q = 0; q < 4; q++) O[mf][nf][q] = 0.f;

    for (int st0 = t0; st0 < S_; st0 += 64) {
        {
            int r = tid >> 2, dg = (tid & 3) * 16;
            const float* qsrc = qb + (size_t)(st0 + r) * D_ + dg;
            const float* vsrc = vb + (size_t)(st0 + r) * D_ + dg;
#pragma unroll
            for (int i = 0; i < 4; i++) {
                float4 v = *(const float4*)(qsrc + i * 4);
                uQ[r * 68 + dg + i * 4 + 0] = to_tf32(v.x);
                uQ[r * 68 + dg + i * 4 + 1] = to_tf32(v.y);
                uQ[r * 68 + dg + i * 4 + 2] = to_tf32(v.z);
                uQ[r * 68 + dg + i * 4 + 3] = to_tf32(v.w);
                float4 w = *(const float4*)(vsrc + i * 4);
                uV[r * 68 + dg + i * 4 + 0] = to_tf32(w.x);
                uV[r * 68 + dg + i * 4 + 1] = to_tf32(w.y);
                uV[r * 68 + dg + i * 4 + 2] = to_tf32(w.z);
                uV[r * 68 + dg + i * 4 + 3] = to_tf32(w.w);
            }
        }
        if (tid < 64) {
            int o = (b * H_ + h) * S_ + st0 + tid;
            srm[tid] = g_m[o]; sinv[tid] = 1.f / g_l[o];
        }
        __syncthreads();
        float c[2][2][4];
#pragma unroll
        for (int mf = 0; mf < 2; mf++)
#pragma unroll
            for (int nf = 0; nf < 2; nf++)
#pragma unroll
                for (int q = 0; q < 4; q++) c[mf][nf][q] = 0.f;
#pragma unroll
        for (int kk = 0; kk < 64; kk += 8) {
            unsigned a[2][4], bf[2][2];
#pragma unroll
            for (int mf = 0; mf < 2; mf++) {
                int mb = wm0 + mf * 16;
                a[mf][0] = uQ[(mb + gr)     * 68 + kk + gc];
                a[mf][1] = uQ[(mb + gr + 8) * 68 + kk + gc];
                a[mf][2] = uQ[(mb + gr)     * 68 + kk + gc + 4];
                a[mf][3] = uQ[(mb + gr + 8) * 68 + kk + gc + 4];
            }
#pragma unroll
            for (int nf = 0; nf < 2; nf++) {
                int nb = wn0 + nf * 8 + gr;
                bf[nf][0] = uK[(kk + gc)     * 68 + nb];
                bf[nf][1] = uK[(kk + gc + 4) * 68 + nb];
            }
#pragma unroll
            for (int mf = 0; mf < 2; mf++)
#pragma unroll
                for (int nf = 0; nf < 2; nf++)
                    mma_tf32(c[mf][nf], a[mf], bf[nf]);
        }
#pragma unroll
        for (int mf = 0; mf < 2; mf++) {
            int sl_a = wm0 + mf * 16 + gr;
            int sl_b = sl_a + 8;
            int gs_a = st0 + sl_a, gs_b = st0 + sl_b;
            float ma = srm[sl_a], ia = sinv[sl_a];
            float mb2 = srm[sl_b], ib = sinv[sl_b];
#pragma unroll
            for (int nf = 0; nf < 2; nf++) {
                int tc = wn0 + nf * 8 + 2 * gc;
                int gt0 = t0 + tc, gt1 = gt0 + 1;
                float p;
                p = (gt0 <= gs_a) ? __expf(c[mf][nf][0] * 0.125f - ma) * ia : 0.f;
                uP[tc * 72 + sl_a] = to_tf32(p);
                p = (gt1 <= gs_a) ? __expf(c[mf][nf][1] * 0.125f - ma) * ia : 0.f;
                uP[(tc + 1) * 72 + sl_a] = to_tf32(p);
                p = (gt0 <= gs_b) ? __expf(c[mf][nf][2] * 0.125f - mb2) * ib : 0.f;
                uP[tc * 72 + sl_b] = to_tf32(p);
                p = (gt1 <= gs_b) ? __expf(c[mf][nf][3] * 0.125f - mb2) * ib : 0.f;
                uP[(tc + 1) * 72 + sl_b] = to_tf32(p);
            }
        }
        __syncthreads();
#pragma unroll
        for (int kk = 0; kk < 64; kk += 8) {
            unsigned a[2][4], bf[2][2];
#pragma unroll
            for (int mf = 0; mf < 2; mf++) {
                int mb = wm0 + mf * 16;
                a[mf][0] = uP[(mb + gr)     * 72 + kk + gc];
                a[mf][1] = uP[(mb + gr + 8) * 72 + kk + gc];
                a[mf][2] = uP[(mb + gr)     * 72 + kk + gc + 4];
                a[mf][3] = uP[(mb + gr + 8) * 72 + kk + gc + 4];
            }
#pragma unroll
            for (int nf = 0; nf < 2; nf++) {
                int nb = wn0 + nf * 8 + gr;
                bf[nf][0] = uV[(kk + gc)     * 68 + nb];
                bf[nf][1] = uV[(kk + gc + 4) * 68 + nb];
            }
#pragma unroll
            for (int mf = 0; mf < 2; mf++)
#pragma unroll
                for (int nf = 0; nf < 2; nf++)
                    mma_tf32(O[mf][nf], a[mf], bf[nf]);
        }
        __syncthreads();
    }
#pragma unroll
    for (int mf = 0; mf < 2; mf++) {
        int trow = t0 + wm0 + mf * 16 + gr;
#pragma unroll
        for (int nf = 0; nf < 2; nf++) {
            int fc = wn0 + nf * 8 + 2 * gc;
            *(float2*)(g_attn + (size_t)(b * S_ + trow) * D_ + h * DH_ + fc)
                = make_float2(O[mf][nf][0], O[mf][nf][1]);
            *(float2*)(g_attn + (size_t)(b * S_ + trow + 8) * D_ + h * DH_ + fc)
                = make_float2(O[mf][nf][2], O[mf][nf][3]);
        }
    }
}

// ---------------- capacity + deterministic slot assignment --------------------
__global__ void capacity_kernel() {
    int tid = threadIdx.x; // 256 = 8 warps, warp per expert
    int w = tid >> 5, lane = tid & 31;
    if (w < E_) {
        int e = w, c = 0;
        for (int i0 = 0; i0 < NTOK * 2; i0 += 32) {
            int i = i0 + lane;
            int idx = g_tk_idx[i];
            bool match = (idx == e);
            unsigned msk = __ballot_sync(0xffffffffu, match);
            if (match) {
                int rank = c + __popc(msk & ((1u << lane) - 1u));
                if (rank < CAP_) {
                    g_slot_token[e * CAP_ + rank] = i >> 1;
                    g_token_slot[i] = e * CAP_ + rank;
                } else {
                    g_token_slot[i] = -1;
                }
            }
            c += __popc(msk);
        }
        if (lane == 0) g_ecount[e] = (c < CAP_) ? c : CAP_;
    }
    __syncthreads();
    for (int t = tid; t < NTOK; t += 256) {
        int s0 = g_token_slot[2 * t], s1 = g_token_slot[2 * t + 1];
        float p0 = (s0 >= 0) ? g_tk_prob[2 * t]     : 0.f;
        float p1 = (s1 >= 0) ? g_tk_prob[2 * t + 1] : 0.f;
        float inv = 1.f / (p0 + p1 + 1e-9f);
        if (s0 >= 0) g_slot_w[s0] = p0 * inv;
        if (s1 >= 0) g_slot_w[s1] = p1 * inv;
    }
}

// ---------------- combine: out = x1 + f (warp per row, float4) -----------------
__global__ void combine_kernel(float* __restrict__ out) {
    int wid = threadIdx.x >> 5, lane = threadIdx.x & 31;
    int row = blockIdx.x * 8 + wid;
    int s0 = g_token_slot[2 * row], s1 = g_token_slot[2 * row + 1];
    const float4* xr = (const float4*)(g_x1 + (size_t)row * D_);
    const float4* f0 = (s0 >= 0) ? (const float4*)(g_sout + (size_t)s0 * D_) : nullptr;
    const float4* f1 = (s1 >= 0) ? (const float4*)(g_sout + (size_t)s1 * D_) : nullptr;
    float4* orow = (float4*)(out + (size_t)row * D_);
#pragma unroll
    for (int i = 0; i < 6; i++) {
        int c = lane + i * 32;
        float4 v = xr[c];
        if (f0) { float4 a = f0[c]; v.x += a.x; v.y += a.y; v.z += a.z; v.w += a.w; }
        if (f1) { float4 a = f1[c]; v.x += a.x; v.y += a.y; v.z += a.z; v.w += a.w; }
        orow[c] = v;
    }
}

// ---------------- aux losses (parallelized) ------------------------------------
__global__ void aux_kernel(float* __restrict__ out, int out_size) {
    __shared__ float ic_sh[E_];
    __shared__ float sa;
    int tid = threadIdx.x, w = tid >> 5, lane = tid & 31;
    if (w < E_) {
        int c = g_ecount[w];
        float s = 0.f;
        for (int r = lane; r < c; r += 32) s += g_slot_w[w * CAP_ + r];
#pragma unroll
        for (int o = 16; o > 0; o >>= 1) s += __shfl_down_sync(0xffffffffu, s, o);
        if (lane == 0) ic_sh[w] = s;
    }
    __syncthreads();
    if (tid == 0) {
        const float scale = 0.01f / 2048.f;
        float es = 0.f;
        for (int i = 0; i < H_ * E_; i++) es += g_hard[i] * scale;
        float a1 = 0.f;
        for (int i = 0; i < H_ * E_; i++) {
            float p = (g_hard[i] * scale) / (es + 1e-9f);
            a1 += p * p;
        }
        a1 *= (float)(E_ * H_);
        float tcs = 0.f, ics = 0.f;
        for (int e = 0; e < E_; e++) { tcs += (float)g_ecount[e]; ics += ic_sh[e]; }
        float a2 = 0.f;
        for (int e = 0; e < E_; e++) a2 += ((float)g_ecount[e] / tcs) * (ic_sh[e] / ics);
        a2 *= (float)E_;
        sa = a1 + a2;
    }
    __syncthreads();
    for (int i = NOUT + tid; i < out_size; i += blockDim.x) out[i] = sa;
}

// ---------------- launch -------------------------------------------------------
extern "C" void kernel_launch(void* const* d_in, const int* in_sizes, int n_in,
                              void* d_out, int out_size) {
    const float* x   = (const float*)d_in[0];
    // d_in[1] = mask (pure causal 0/-1e9, applied analytically)
    const float* Wq  = (const float*)d_in[2];
    const float* Wk  = (const float*)d_in[3];
    const float* Wv  = (const float*)d_in[4];
    const float* Wo  = (const float*)d_in[5];
    const float* Wr  = (const float*)d_in[6];
    const float* g1  = (const float*)d_in[7];
    const float* b1  = (const float*)d_in[8];
    const float* g2  = (const float*)d_in[9];
    const float* b2  = (const float*)d_in[10];
    const float* gff = (const float*)d_in[11];
    const float* W1  = (const float*)d_in[12];
    const float* W2  = (const float*)d_in[13];
    float* out = (float*)d_out;

    float *p_xln, *p_x1, *p_xln2;
    cudaGetSymbolAddress((void**)&p_xln,  g_xln);
    cudaGetSymbolAddress((void**)&p_x1,   g_x1);
    cudaGetSymbolAddress((void**)&p_xln2, g_xln2);

    const int pass1_smem = (2 * 64 * 68 + 64 * 72) * 4;
    const int pass2_smem = (3 * 64 * 68 + 64 * 72 + 128) * 4;
    cudaFuncSetAttribute(attn_pass1, cudaFuncAttributeMaxDynamicSharedMemorySize, pass1_smem);
    cudaFuncSetAttribute(attn_pass2, cudaFuncAttributeMaxDynamicSharedMemorySize, pass2_smem);

    ln_kernel<<<NTOK / 8, 256>>>(x, g1, b1, p_xln, 1);
    gemm_tf32<0><<<dim3(26, NTOK / 128, 1), 256>>>(Wq, Wk, Wr);   // Q, K, router fused
    router_argmax<<<(NTOK * H_ + 255) / 256, 256>>>();
    vsel_kernel<<<NTOK, 384>>>(Wv);
    attn_pass1<<<dim3(S_ / 64, H_, B_), 256, pass1_smem>>>();
    attn_pass2<<<dim3(S_ / 64, H_, B_), 256, pass2_smem>>>();
    osel_kernel<<<NTOK, 384>>>(Wo, x);
    ln_gate_kernel<<<NTOK / 8, 256>>>(p_x1, g2, b2, gff, p_xln2);
    capacity_kernel<<<1, 256>>>();
    gemm_tf32<1><<<dim3(DFF_ / 64, (CAP_ + 127) / 128, E_), 256>>>(W1, nullptr, nullptr);
    gemm_tf32<2><<<dim3(D_ / 64, (CAP_ + 127) / 128, E_), 256>>>(W2, nullptr, nullptr);
    combine_kernel<<<NTOK / 8, 256>>>(out);
    if (out_size > NOUT) aux_kernel<<<1, 256>>>(out, out_size);
}

// round 11
// speedup vs baseline: 1.4714x; 1.4714x over previous
#include <cuda_runtime.h>
#include <math.h>

#define B_ 2
#define S_ 1024
#define D_ 768
#define H_ 12
#define E_ 8
#define DH_ 64
#define DFF_ 2048
#define NTOK (B_*S_)
#define CAP_ 320
#define NOUT (NTOK*D_)

// ---------------- scratch (device globals; no allocation allowed) -------------
__device__ float g_xln [NTOK*D_];
__device__ float g_q   [NTOK*D_];
__device__ float g_k   [NTOK*D_];
__device__ float g_vsel[NTOK*D_];
__device__ float g_attn[NTOK*D_];
__device__ float g_x1  [NTOK*D_];
__device__ float g_xln2[NTOK*D_];
__device__ float g_rlog[NTOK*(H_*E_)];
__device__ int   g_eidx[NTOK*H_];
__device__ int   g_hard[H_*E_];
__device__ float g_m[B_*H_*S_];
__device__ float g_l[B_*H_*S_];
__device__ int   g_tk_idx[NTOK*2];
__device__ float g_tk_prob[NTOK*2];
__device__ int   g_token_slot[NTOK*2];
__device__ int   g_slot_token[E_*CAP_];
__device__ float g_slot_w[E_*CAP_];
__device__ int   g_ecount[E_];
__device__ float g_hbuf[E_*CAP_*DFF_];
__device__ float g_sout[E_*CAP_*D_];

// ---------------- tf32 tensor-core helpers -------------------------------------
__device__ __forceinline__ unsigned to_tf32(float f) {
    unsigned u; asm("cvt.rna.tf32.f32 %0,%1;" : "=r"(u) : "f"(f)); return u;
}
__device__ __forceinline__ void mma_tf32(float c[4], const unsigned a[4], const unsigned b[2]) {
    asm("mma.sync.aligned.m16n8k8.row.col.f32.tf32.tf32.f32 "
        "{%0,%1,%2,%3},{%4,%5,%6,%7},{%8,%9},{%0,%1,%2,%3};"
        : "+f"(c[0]), "+f"(c[1]), "+f"(c[2]), "+f"(c[3])
        : "r"(a[0]), "r"(a[1]), "r"(a[2]), "r"(a[3]), "r"(b[0]), "r"(b[1]));
}

// ---------------- LayerNorm (warp per row, float4); optional g_hard clear ------
__global__ void ln_kernel(const float* __restrict__ x, const float* __restrict__ g,
                          const float* __restrict__ b, float* __restrict__ out,
                          int clear_hard) {
    if (clear_hard && blockIdx.x == 0 && threadIdx.x < H_ * E_) g_hard[threadIdx.x] = 0;
    int wid = threadIdx.x >> 5, lane = threadIdx.x & 31;
    int row = blockIdx.x * 8 + wid;
    const float4* xr = (const float4*)(x + (size_t)row * D_);
    float4 v[6];
    float s = 0.f, s2 = 0.f;
#pragma unroll
    for (int i = 0; i < 6; i++) {
        v[i] = xr[lane + i * 32];
        s  += v[i].x + v[i].y + v[i].z + v[i].w;
        s2 += v[i].x * v[i].x + v[i].y * v[i].y + v[i].z * v[i].z + v[i].w * v[i].w;
    }
#pragma unroll
    for (int o = 16; o > 0; o >>= 1) {
        s  += __shfl_xor_sync(0xffffffffu, s,  o);
        s2 += __shfl_xor_sync(0xffffffffu, s2, o);
    }
    float mean = s * (1.f / D_);
    float inv  = rsqrtf(s2 * (1.f / D_) - mean * mean + 1e-5f);
    float4* orow = (float4*)(out + (size_t)row * D_);
    const float4* g4 = (const float4*)g;
    const float4* b4 = (const float4*)b;
#pragma unroll
    for (int i = 0; i < 6; i++) {
        float4 gg = g4[lane + i * 32], bb = b4[lane + i * 32];
        float4 o;
        o.x = (v[i].x - mean) * inv * gg.x + bb.x;
        o.y = (v[i].y - mean) * inv * gg.y + bb.y;
        o.z = (v[i].z - mean) * inv * gg.z + bb.z;
        o.w = (v[i].w - mean) * inv * gg.w + bb.w;
        orow[lane + i * 32] = o;
    }
}

// ---------------- tf32 tensor-core GEMM, 128x64x16 tiles (single buffer) -------
// MODE 0: fused QKR. bx<12: Wq->g_q | bx<24: Wk->g_k | bx>=24: Wr->g_rlog (N=96)
// MODE 1: FFN GEMM1 (gathered A rows, ReLU). z=e. B=W1[e]. C=g_hbuf[e].
// MODE 2: FFN GEMM2 (slot-weight scale).     z=e. B=W2[e]. C=g_sout[e].
#define ASTRIDE 20
#define BSTRIDE 72
template<int MODE>
__global__ __launch_bounds__(256)
void gemm_tf32(const float* __restrict__ P0, const float* __restrict__ P1,
               const float* __restrict__ P2) {
    __shared__ __align__(16) unsigned As[128 * ASTRIDE];
    __shared__ __align__(16) unsigned Bs[16 * BSTRIDE];

    const int tid = threadIdx.x, wid = tid >> 5, lane = tid & 31;
    const int e  = blockIdx.z;
    const int m0 = blockIdx.y * 128;

    int N, K, count, n0;
    const float* Bm;
    float* C;
    const float* Abase;
    if (MODE == 0) {
        K = D_; count = NTOK; Abase = g_xln;
        int bx = blockIdx.x;
        if (bx < 12)      { Bm = P0; C = g_q;    N = D_; n0 = bx * 64; }
        else if (bx < 24) { Bm = P1; C = g_k;    N = D_; n0 = (bx - 12) * 64; }
        else              { Bm = P2; C = g_rlog; N = 96; n0 = (bx - 24) * 64; }
    } else if (MODE == 1) {
        N = DFF_; K = D_; count = g_ecount[e]; n0 = blockIdx.x * 64;
        if (count <= 0 || m0 >= count) return;
        Bm = P0 + (size_t)e * D_ * DFF_;
        C  = g_hbuf + (size_t)e * CAP_ * DFF_;
        Abase = g_xln2;
    } else {
        N = D_; K = DFF_; count = g_ecount[e]; n0 = blockIdx.x * 64;
        if (count <= 0 || m0 >= count) return;
        Bm = P0 + (size_t)e * DFF_ * D_;
        C  = g_sout + (size_t)e * CAP_ * D_;
        Abase = g_hbuf + (size_t)e * CAP_ * DFF_;
    }

    const int sm_r = tid >> 1;
    const int sm_k = (tid & 1) * 8;
    const int brow = tid >> 4;
    const int bcol = (tid & 15) * 4;

    const float* Aptr;
    {
        int r = m0 + sm_r;
        if (r >= count) r = count - 1;
        if (MODE == 1)
            Aptr = Abase + (size_t)g_slot_token[e * CAP_ + r] * D_ + sm_k;
        else
            Aptr = Abase + (size_t)r * K + sm_k;
    }
    int bc_eff = bcol;
    if (n0 + bcol + 4 > N) bc_eff = N - 4 - n0;
    const float* Bptr = Bm + (size_t)brow * N + n0 + bc_eff;

    const int wm0 = (wid & 3) * 32;
    const int wn0 = (wid >> 2) * 32;
    const int gr = lane >> 2, gc = lane & 3;

    float acc[2][4][4];
#pragma unroll
    for (int i = 0; i < 2; i++)
#pragma unroll
        for (int j = 0; j < 4; j++)
#pragma unroll
            for (int q = 0; q < 4; q++) acc[i][j][q] = 0.f;

    for (int k0 = 0; k0 < K; k0 += 16) {
        float4 av0 = *(const float4*)(Aptr + k0);
        float4 av1 = *(const float4*)(Aptr + k0 + 4);
        float4 bv  = *(const float4*)(Bptr + (size_t)k0 * N);
        uint4 u0 = make_uint4(to_tf32(av0.x), to_tf32(av0.y), to_tf32(av0.z), to_tf32(av0.w));
        uint4 u1 = make_uint4(to_tf32(av1.x), to_tf32(av1.y), to_tf32(av1.z), to_tf32(av1.w));
        uint4 ub = make_uint4(to_tf32(bv.x),  to_tf32(bv.y),  to_tf32(bv.z),  to_tf32(bv.w));
        *(uint4*)&As[sm_r * ASTRIDE + sm_k]     = u0;
        *(uint4*)&As[sm_r * ASTRIDE + sm_k + 4] = u1;
        *(uint4*)&Bs[brow * BSTRIDE + bcol]     = ub;
        __syncthreads();
#pragma unroll
        for (int kk = 0; kk < 16; kk += 8) {
            unsigned a[2][4];
#pragma unroll
            for (int mf = 0; mf < 2; mf++) {
                int mb = wm0 + mf * 16;
                a[mf][0] = As[(mb + gr)     * ASTRIDE + kk + gc];
                a[mf][1] = As[(mb + gr + 8) * ASTRIDE + kk + gc];
                a[mf][2] = As[(mb + gr)     * ASTRIDE + kk + gc + 4];
                a[mf][3] = As[(mb + gr + 8) * ASTRIDE + kk + gc + 4];
            }
#pragma unroll
            for (int nf = 0; nf < 4; nf++) {
                int nb = wn0 + nf * 8 + gr;
                unsigned b[2];
                b[0] = Bs[(kk + gc)     * BSTRIDE + nb];
                b[1] = Bs[(kk + gc + 4) * BSTRIDE + nb];
                mma_tf32(acc[0][nf], a[0], b);
                mma_tf32(acc[1][nf], a[1], b);
            }
        }
        __syncthreads();
    }

#pragma unroll
    for (int mf = 0; mf < 2; mf++) {
        int rbase = m0 + wm0 + mf * 16 + gr;
#pragma unroll
        for (int half = 0; half < 2; half++) {
            int r = rbase + half * 8;
            if (MODE != 0 && r >= count) continue;
            float w = 1.f;
            if (MODE == 2) w = g_slot_w[e * CAP_ + r];
#pragma unroll
            for (int nf = 0; nf < 4; nf++) {
                int cc = n0 + wn0 + nf * 8 + gc * 2;
                if (MODE == 0 && cc + 2 > N) continue;
                float v0 = acc[mf][nf][half * 2 + 0];
                float v1 = acc[mf][nf][half * 2 + 1];
                if (MODE == 1) { v0 = fmaxf(v0, 0.f); v1 = fmaxf(v1, 0.f); }
                else if (MODE == 2) { v0 *= w; v1 *= w; }
                *(float2*)(C + (size_t)r * N + cc) = make_float2(v0, v1);
            }
        }
    }
}

__global__ void router_argmax() {
    int idx = blockIdx.x * 256 + threadIdx.x;
    if (idx >= NTOK * H_) return;
    int row = idx / H_, h = idx - row * H_;
    const float* lg = g_rlog + (size_t)row * 96 + h * 8;
    float best = lg[0]; int bi = 0;
#pragma unroll
    for (int e = 1; e < E_; e++) { float v = lg[e]; if (v > best) { best = v; bi = e; } }
    g_eidx[row * H_ + h] = bi;
    atomicAdd(&g_hard[h * E_ + bi], 1);
}

// ---------------- per (token, head) expert matvecs — 2 tokens per block --------
__global__ void vsel_kernel(const float* __restrict__ Wv) {
    int row0 = blockIdx.x * 2, tid = threadIdx.x;
    int h = tid >> 5, lane = tid & 31;
    int e0 = g_eidx[row0 * H_ + h];
    int e1 = g_eidx[(row0 + 1) * H_ + h];
    const float* wv0 = Wv + (size_t)(h * E_ + e0) * DH_ * DH_;
    const float* wv1 = Wv + (size_t)(h * E_ + e1) * DH_ * DH_;
    const float* x0 = g_xln + (size_t)row0 * D_ + h * DH_;
    const float* x1 = x0 + D_;
    float a0 = 0.f, b0 = 0.f, a1 = 0.f, b1 = 0.f;
    if (e0 == e1) {
#pragma unroll 4
        for (int d = 0; d < DH_; d++) {
            float wA = wv0[d * DH_ + lane], wB = wv0[d * DH_ + lane + 32];
            float v0 = x0[d], v1 = x1[d];
            a0 += v0 * wA; b0 += v0 * wB;
            a1 += v1 * wA; b1 += v1 * wB;
        }
    } else {
#pragma unroll 4
        for (int d = 0; d < DH_; d++) {
            float v0 = x0[d], v1 = x1[d];
            a0 += v0 * wv0[d * DH_ + lane];
            b0 += v0 * wv0[d * DH_ + lane + 32];
            a1 += v1 * wv1[d * DH_ + lane];
            b1 += v1 * wv1[d * DH_ + lane + 32];
        }
    }
    size_t o = (size_t)row0 * D_ + h * DH_ + lane;
    g_vsel[o]           = a0; g_vsel[o + 32]      = b0;
    g_vsel[o + D_]      = a1; g_vsel[o + D_ + 32] = b1;
}

__global__ void osel_kernel(const float* __restrict__ Wo, const float* __restrict__ x) {
    int row0 = blockIdx.x * 2, tid = threadIdx.x;
    int h = tid >> 5, lane = tid & 31;
    int e0 = g_eidx[row0 * H_ + h];
    int e1 = g_eidx[(row0 + 1) * H_ + h];
    const float* wo0 = Wo + (size_t)(h * E_ + e0) * DH_ * DH_;
    const float* wo1 = Wo + (size_t)(h * E_ + e1) * DH_ * DH_;
    const float* a0p = g_attn + (size_t)row0 * D_ + h * DH_;
    const float* a1p = a0p + D_;
    float a0 = 0.f, b0 = 0.f, a1 = 0.f, b1 = 0.f;
    if (e0 == e1) {
#pragma unroll 4
        for (int f = 0; f < DH_; f++) {
            float wA = wo0[f * DH_ + lane], wB = wo0[f * DH_ + lane + 32];
            float v0 = a0p[f], v1 = a1p[f];
            a0 += v0 * wA; b0 += v0 * wB;
            a1 += v1 * wA; b1 += v1 * wB;
        }
    } else {
#pragma unroll 4
        for (int f = 0; f < DH_; f++) {
            float v0 = a0p[f], v1 = a1p[f];
            a0 += v0 * wo0[f * DH_ + lane];
            b0 += v0 * wo0[f * DH_ + lane + 32];
            a1 += v1 * wo1[f * DH_ + lane];
            b1 += v1 * wo1[f * DH_ + lane + 32];
        }
    }
    size_t o = (size_t)row0 * D_ + h * DH_ + lane;
    g_x1[o]           = x[o]           + a0;
    g_x1[o + 32]      = x[o + 32]      + b0;
    g_x1[o + D_]      = x[o + D_]      + a1;
    g_x1[o + D_ + 32] = x[o + D_ + 32] + b1;
}

// ---------------- attention pass 1 (tf32 MMA): row stats m_s, l_s --------------
__global__ __launch_bounds__(256)
void attn_pass1() {
    extern __shared__ unsigned dsp[];
    unsigned* uQ = dsp;
    unsigned* uK = dsp + 64 * 68;
    float* Ss = (float*)(dsp + 2 * 64 * 68);
    int s0 = blockIdx.x * 64, h = blockIdx.y, b = blockIdx.z;
    int tid = threadIdx.x, wid = tid >> 5, lane = tid & 31;
    int gr = lane >> 2, gc = lane & 3;
    const float* qb = g_q + (size_t)b * S_ * D_ + h * DH_;
    const float* kb = g_k + (size_t)b * S_ * D_ + h * DH_;
    {
        int r = tid >> 2, dg = (tid & 3) * 16;
        const float* src = qb + (size_t)(s0 + r) * D_ + dg;
#pragma unroll
        for (int i = 0; i < 4; i++) {
            float4 v = *(const float4*)(src + i * 4);
            uQ[r * 68 + dg + i * 4 + 0] = to_tf32(v.x);
            uQ[r * 68 + dg + i * 4 + 1] = to_tf32(v.y);
            uQ[r * 68 + dg + i * 4 + 2] = to_tf32(v.z);
            uQ[r * 68 + dg + i * 4 + 3] = to_tf32(v.w);
        }
    }
    const int wm0 = (wid & 1) * 32, wn0 = (wid >> 1) * 16;
    const int rr = tid >> 2, qq = tid & 3;
    float run_m = -INFINITY, run_l = 0.f;

    for (int t0 = 0; t0 <= s0; t0 += 64) {
        {
            int r = tid >> 2, dg = (tid & 3) * 16;
            const float* src = kb + (size_t)(t0 + r) * D_ + dg;
#pragma unroll
            for (int i = 0; i < 4; i++) {
                float4 v = *(const float4*)(src + i * 4);
                uK[(dg + i * 4 + 0) * 68 + r] = to_tf32(v.x);
                uK[(dg + i * 4 + 1) * 68 + r] = to_tf32(v.y);
                uK[(dg + i * 4 + 2) * 68 + r] = to_tf32(v.z);
                uK[(dg + i * 4 + 3) * 68 + r] = to_tf32(v.w);
            }
        }
        __syncthreads();
        float c[2][2][4];
#pragma unroll
        for (int mf = 0; mf < 2; mf++)
#pragma unroll
            for (int nf = 0; nf < 2; nf++)
#pragma unroll
                for (int q = 0; q < 4; q++) c[mf][nf][q] = 0.f;
#pragma unroll
        for (int kk = 0; kk < 64; kk += 8) {
            unsigned a[2][4], bf[2][2];
#pragma unroll
            for (int mf = 0; mf < 2; mf++) {
                int mb = wm0 + mf * 16;
                a[mf][0] = uQ[(mb + gr)     * 68 + kk + gc];
                a[mf][1] = uQ[(mb + gr + 8) * 68 + kk + gc];
                a[mf][2] = uQ[(mb + gr)     * 68 + kk + gc + 4];
                a[mf][3] = uQ[(mb + gr + 8) * 68 + kk + gc + 4];
            }
#pragma unroll
            for (int nf = 0; nf < 2; nf++) {
                int nb = wn0 + nf * 8 + gr;
                bf[nf][0] = uK[(kk + gc)     * 68 + nb];
                bf[nf][1] = uK[(kk + gc + 4) * 68 + nb];
            }
#pragma unroll
            for (int mf = 0; mf < 2; mf++)
#pragma unroll
                for (int nf = 0; nf < 2; nf++)
                    mma_tf32(c[mf][nf], a[mf], bf[nf]);
        }
#pragma unroll
        for (int mf = 0; mf < 2; mf++)
#pragma unroll
            for (int nf = 0; nf < 2; nf++) {
                int row = wm0 + mf * 16 + gr, col = wn0 + nf * 8 + 2 * gc;
                *(float2*)&Ss[row * 72 + col]       = make_float2(c[mf][nf][0], c[mf][nf][1]);
                *(float2*)&Ss[(row + 8) * 72 + col] = make_float2(c[mf][nf][2], c[mf][nf][3]);
            }
        __syncthreads();
        float v[16];
#pragma unroll
        for (int i = 0; i < 4; i++) {
            float4 t4 = *(const float4*)&Ss[rr * 72 + qq * 16 + i * 4];
            v[i * 4 + 0] = t4.x; v[i * 4 + 1] = t4.y; v[i * 4 + 2] = t4.z; v[i * 4 + 3] = t4.w;
        }
        int gs = s0 + rr;
        float mx = -INFINITY;
#pragma unroll
        for (int cI = 0; cI < 16; cI++) {
            int gt = t0 + qq * 16 + cI;
            if (gt <= gs) mx = fmaxf(mx, v[cI] * 0.125f);
        }
        mx = fmaxf(mx, __shfl_xor_sync(0xffffffffu, mx, 1));
        mx = fmaxf(mx, __shfl_xor_sync(0xffffffffu, mx, 2));
        float mn = fmaxf(run_m, mx);
        float alpha = __expf(run_m - mn);
        float sum = 0.f;
#pragma unroll
        for (int cI = 0; cI < 16; cI++) {
            int gt = t0 + qq * 16 + cI;
            if (gt <= gs) sum += __expf(v[cI] * 0.125f - mn);
        }
        sum += __shfl_xor_sync(0xffffffffu, sum, 1);
        sum += __shfl_xor_sync(0xffffffffu, sum, 2);
        run_l = run_l * alpha + sum;
        run_m = mn;
    }
    if (qq == 0) {
        int o = (b * H_ + h) * S_ + s0 + rr;
        g_m[o] = run_m; g_l[o] = run_l;
    }
}

// ---------------- attention pass 2 (tf32 MMA): out[t] = sum_s P[s,t] v[s] ------
__global__ __launch_bounds__(256)
void attn_pass2() {
    extern __shared__ unsigned dsp2[];
    unsigned* uK = dsp2;
    unsigned* uQ = dsp2 + 4352;
    unsigned* uV = dsp2 + 8704;
    unsigned* uP = dsp2 + 13056;
    float* srm  = (float*)(dsp2 + 17664);
    float* sinv = srm + 64;
    int t0 = blockIdx.x * 64, h = blockIdx.y, b = blockIdx.z;
    int tid = threadIdx.x, wid = tid >> 5, lane = tid & 31;
    int gr = lane >> 2, gc = lane & 3;
    const float* qb = g_q    + (size_t)b * S_ * D_ + h * DH_;
    const float* kb = g_k    + (size_t)b * S_ * D_ + h * DH_;
    const float* vb = g_vsel + (size_t)b * S_ * D_ + h * DH_;
    {
        int r = tid >> 2, dg = (tid & 3) * 16;
        const float* src = kb + (size_t)(t0 + r) * D_ + dg;
#pragma unroll
        for (int i = 0; i < 4; i++) {
            float4 v = *(const float4*)(src + i * 4);
            uK[(dg + i * 4 + 0) * 68 + r] = to_tf32(v.x);
            uK[(dg + i * 4 + 1) * 68 + r] = to_tf32(v.y);
            uK[(dg + i * 4 + 2) * 68 + r] = to_tf32(v.z);
            uK[(dg + i * 4 + 3) * 68 + r] = to_tf32(v.w);
        }
    }
    const int wm0 = (wid & 1) * 32, wn0 = (wid >> 1) * 16;
    float O[2][2][4];
#pragma unroll
    for (int mf = 0; mf < 2; mf++)
#pragma unroll
        for (int nf = 0; nf < 2; nf++)
#pragma unroll
            for (int q = 0; q < 4; q++) O[mf][nf][q] = 0.f;

    for (int st0 = t0; st0 < S_; st0 += 64) {
        {
            int r = tid >> 2, dg = (tid & 3) * 16;
            const float* qsrc = qb + (size_t)(st0 + r) * D_ + dg;
            const float* vsrc = vb + (size_t)(st0 + r) * D_ + dg;
#pragma unroll
            for (int i = 0; i < 4; i++) {
                float4 v = *(const float4*)(qsrc + i * 4);
                uQ[r * 68 + dg + i * 4 + 0] = to_tf32(v.x);
                uQ[r * 68 + dg + i * 4 + 1] = to_tf32(v.y);
                uQ[r * 68 + dg + i * 4 + 2] = to_tf32(v.z);
                uQ[r * 68 + dg + i * 4 + 3] = to_tf32(v.w);
                float4 w = *(const float4*)(vsrc + i * 4);
                uV[r * 68 + dg + i * 4 + 0] = to_tf32(w.x);
                uV[r * 68 + dg + i * 4 + 1] = to_tf32(w.y);
                uV[r * 68 + dg + i * 4 + 2] = to_tf32(w.z);
                uV[r * 68 + dg + i * 4 + 3] = to_tf32(w.w);
            }
        }
        if (tid < 64) {
            int o = (b * H_ + h) * S_ + st0 + tid;
            srm[tid] = g_m[o]; sinv[tid] = 1.f / g_l[o];
        }
        __syncthreads();
        float c[2][2][4];
#pragma unroll
        for (int mf = 0; mf < 2; mf++)
#pragma unroll
            for (int nf = 0; nf < 2; nf++)
#pragma unroll
                for (int q = 0; q < 4; q++) c[mf][nf][q] = 0.f;
#pragma unroll
        for (int kk = 0; kk < 64; kk += 8) {
            unsigned a[2][4], bf[2][2];
#pragma unroll
            for (int mf = 0; mf < 2; mf++) {
                int mb = wm0 + mf * 16;
                a[mf][0] = uQ[(mb + gr)     * 68 + kk + gc];
                a[mf][1] = uQ[(mb + gr + 8) * 68 + kk + gc];
                a[mf][2] = uQ[(mb + gr)     * 68 + kk + gc + 4];
                a[mf][3] = uQ[(mb + gr + 8) * 68 + kk + gc + 4];
            }
#pragma unroll
            for (int nf = 0; nf < 2; nf++) {
                int nb = wn0 + nf * 8 + gr;
                bf[nf][0] = uK[(kk + gc)     * 68 + nb];
                bf[nf][1] = uK[(kk + gc + 4) * 68 + nb];
            }
#pragma unroll
            for (int mf = 0; mf < 2; mf++)
#pragma unroll
                for (int nf = 0; nf < 2; nf++)
                    mma_tf32(c[mf][nf], a[mf], bf[nf]);
        }
#pragma unroll
        for (int mf = 0; mf < 2; mf++) {
            int sl_a = wm0 + mf * 16 + gr;
            int sl_b = sl_a + 8;
            int gs_a = st0 + sl_a, gs_b = st0 + sl_b;
            float ma = srm[sl_a], ia = sinv[sl_a];
            float mb2 = srm[sl_b], ib = sinv[sl_b];
#pragma unroll
            for (int nf = 0; nf < 2; nf++) {
                int tc = wn0 + nf * 8 + 2 * gc;
                int gt0 = t0 + tc, gt1 = gt0 + 1;
                float p;
                p = (gt0 <= gs_a) ? __expf(c[mf][nf][0] * 0.125f - ma) * ia : 0.f;
                uP[tc * 72 + sl_a] = to_tf32(p);
                p = (gt1 <= gs_a) ? __expf(c[mf][nf][1] * 0.125f - ma) * ia : 0.f;
                uP[(tc + 1) * 72 + sl_a] = to_tf32(p);
                p = (gt0 <= gs_b) ? __expf(c[mf][nf][2] * 0.125f - mb2) * ib : 0.f;
                uP[tc * 72 + sl_b] = to_tf32(p);
                p = (gt1 <= gs_b) ? __expf(c[mf][nf][3] * 0.125f - mb2) * ib : 0.f;
                uP[(tc + 1) * 72 + sl_b] = to_tf32(p);
            }
        }
        __syncthreads();
#pragma unroll
        for (int kk = 0; kk < 64; kk += 8) {
            unsigned a[2][4], bf[2][2];
#pragma unroll
            for (int mf = 0; mf < 2; mf++) {
                int mb = wm0 + mf * 16;
                a[mf][0] = uP[(mb + gr)     * 72 + kk + gc];
                a[mf][1] = uP[(mb + gr + 8) * 72 + kk + gc];
                a[mf][2] = uP[(mb + gr)     * 72 + kk + gc + 4];
                a[mf][3] = uP[(mb + gr + 8) * 72 + kk + gc + 4];
            }
#pragma unroll
            for (int nf = 0; nf < 2; nf++) {
                int nb = wn0 + nf * 8 + gr;
                bf[nf][0] = uV[(kk + gc)     * 68 + nb];
                bf[nf][1] = uV[(kk + gc + 4) * 68 + nb];
            }
#pragma unroll
            for (int mf = 0; mf < 2; mf++)
#pragma unroll
                for (int nf = 0; nf < 2; nf++)
                    mma_tf32(O[mf][nf], a[mf], bf[nf]);
        }
        __syncthreads();
    }
#pragma unroll
    for (int mf = 0; mf < 2; mf++) {
        int trow = t0 + wm0 + mf * 16 + gr;
#pragma unroll
        for (int nf = 0; nf < 2; nf++) {
            int fc = wn0 + nf * 8 + 2 * gc;
            *(float2*)(g_attn + (size_t)(b * S_ + trow) * D_ + h * DH_ + fc)
                = make_float2(O[mf][nf][0], O[mf][nf][1]);
            *(float2*)(g_attn + (size_t)(b * S_ + trow + 8) * D_ + h * DH_ + fc)
                = make_float2(O[mf][nf][2], O[mf][nf][3]);
        }
    }
}

// ---------------- FFN gate + top-2 (warp per token) ----------------------------
__global__ void gate_kernel(const float* __restrict__ gff) {
    int wid = threadIdx.x >> 5, lane = threadIdx.x & 31;
    int row = blockIdx.x * 8 + wid;
    const float* xr = g_xln2 + (size_t)row * D_;
    float acc[8] = {};
    for (int d = lane; d < D_; d += 32) {
        float xv = xr[d];
        float4 gA = *(const float4*)(gff + (size_t)d * E_);
        float4 gB = *(const float4*)(gff + (size_t)d * E_ + 4);
        acc[0] += xv * gA.x; acc[1] += xv * gA.y; acc[2] += xv * gA.z; acc[3] += xv * gA.w;
        acc[4] += xv * gB.x; acc[5] += xv * gB.y; acc[6] += xv * gB.z; acc[7] += xv * gB.w;
    }
#pragma unroll
    for (int off = 16; off > 0; off >>= 1)
#pragma unroll
        for (int i = 0; i < 8; i++)
            acc[i] += __shfl_down_sync(0xffffffffu, acc[i], off);
    if (lane == 0) {
        int i0 = 0; float v0 = acc[0];
#pragma unroll
        for (int e = 1; e < E_; e++) if (acc[e] > v0) { v0 = acc[e]; i0 = e; }
        int i1 = -1; float v1 = -3.4e38f;
#pragma unroll
        for (int e = 0; e < E_; e++) { if (e == i0) continue; if (acc[e] > v1) { v1 = acc[e]; i1 = e; } }
        float e1 = expf(v1 - v0);
        float z = 1.f + e1;
        g_tk_idx[row * 2] = i0; g_tk_idx[row * 2 + 1] = i1;
        g_tk_prob[row * 2] = 1.f / z; g_tk_prob[row * 2 + 1] = e1 / z;
    }
}

// ---------------- capacity + deterministic slot assignment --------------------
__global__ void capacity_kernel() {
    int tid = threadIdx.x; // 256 = 8 warps, warp per expert
    int w = tid >> 5, lane = tid & 31;
    if (w < E_) {
        int e = w, c = 0;
        for (int i0 = 0; i0 < NTOK * 2; i0 += 32) {
            int i = i0 + lane;
            int idx = g_tk_idx[i];
            bool match = (idx == e);
            unsigned msk = __ballot_sync(0xffffffffu, match);
            if (match) {
                int rank = c + __popc(msk & ((1u << lane) - 1u));
                if (rank < CAP_) {
                    g_slot_token[e * CAP_ + rank] = i >> 1;
                    g_token_slot[i] = e * CAP_ + rank;
                } else {
                    g_token_slot[i] = -1;
                }
            }
            c += __popc(msk);
        }
        if (lane == 0) g_ecount[e] = (c < CAP_) ? c : CAP_;
    }
    __syncthreads();
    for (int t = tid; t < NTOK; t += 256) {
        int s0 = g_token_slot[2 * t], s1 = g_token_slot[2 * t + 1];
        float p0 = (s0 >= 0) ? g_tk_prob[2 * t]     : 0.f;
        float p1 = (s1 >= 0) ? g_tk_prob[2 * t + 1] : 0.f;
        float inv = 1.f / (p0 + p1 + 1e-9f);
        if (s0 >= 0) g_slot_w[s0] = p0 * inv;
        if (s1 >= 0) g_slot_w[s1] = p1 * inv;
    }
}

// ---------------- combine: out = x1 + f (warp per row, float4) -----------------
__global__ void combine_kernel(float* __restrict__ out) {
    int wid = threadIdx.x >> 5, lane = threadIdx.x & 31;
    int row = blockIdx.x * 8 + wid;
    int s0 = g_token_slot[2 * row], s1 = g_token_slot[2 * row + 1];
    const float4* xr = (const float4*)(g_x1 + (size_t)row * D_);
    const float4* f0 = (s0 >= 0) ? (const float4*)(g_sout + (size_t)s0 * D_) : nullptr;
    const float4* f1 = (s1 >= 0) ? (const float4*)(g_sout + (size_t)s1 * D_) : nullptr;
    float4* orow = (float4*)(out + (size_t)row * D_);
#pragma unroll
    for (int i = 0; i < 6; i++) {
        int c = lane + i * 32;
        float4 v = xr[c];
        if (f0) { float4 a = f0[c]; v.x += a.x; v.y += a.y; v.z += a.z; v.w += a.w; }
        if (f1) { float4 a = f1[c]; v.x += a.x; v.y += a.y; v.z += a.z; v.w += a.w; }
        orow[c] = v;
    }
}

// ---------------- aux losses (parallelized) ------------------------------------
__global__ void aux_kernel(float* __restrict__ out, int out_size) {
    __shared__ float ic_sh[E_];
    __shared__ float sa;
    int tid = threadIdx.x, w = tid >> 5, lane = tid & 31;
    if (w < E_) {
        int c = g_ecount[w];
        float s = 0.f;
        for (int r = lane; r < c; r += 32) s += g_slot_w[w * CAP_ + r];
#pragma unroll
        for (int o = 16; o > 0; o >>= 1) s += __shfl_down_sync(0xffffffffu, s, o);
        if (lane == 0) ic_sh[w] = s;
    }
    __syncthreads();
    if (tid == 0) {
        const float scale = 0.01f / 2048.f;
        float es = 0.f;
        for (int i = 0; i < H_ * E_; i++) es += g_hard[i] * scale;
        float a1 = 0.f;
        for (int i = 0; i < H_ * E_; i++) {
            float p = (g_hard[i] * scale) / (es + 1e-9f);
            a1 += p * p;
        }
        a1 *= (float)(E_ * H_);
        float tcs = 0.f, ics = 0.f;
        for (int e = 0; e < E_; e++) { tcs += (float)g_ecount[e]; ics += ic_sh[e]; }
        float a2 = 0.f;
        for (int e = 0; e < E_; e++) a2 += ((float)g_ecount[e] / tcs) * (ic_sh[e] / ics);
        a2 *= (float)E_;
        sa = a1 + a2;
    }
    __syncthreads();
    for (int i = NOUT + tid; i < out_size; i += blockDim.x) out[i] = sa;
}

// ---------------- launch -------------------------------------------------------
extern "C" void kernel_launch(void* const* d_in, const int* in_sizes, int n_in,
                              void* d_out, int out_size) {
    const float* x   = (const float*)d_in[0];
    // d_in[1] = mask (pure causal 0/-1e9, applied analytically)
    const float* Wq  = (const float*)d_in[2];
    const float* Wk  = (const float*)d_in[3];
    const float* Wv  = (const float*)d_in[4];
    const float* Wo  = (const float*)d_in[5];
    const float* Wr  = (const float*)d_in[6];
    const float* g1  = (const float*)d_in[7];
    const float* b1  = (const float*)d_in[8];
    const float* g2  = (const float*)d_in[9];
    const float* b2  = (const float*)d_in[10];
    const float* gff = (const float*)d_in[11];
    const float* W1  = (const float*)d_in[12];
    const float* W2  = (const float*)d_in[13];
    float* out = (float*)d_out;

    float *p_xln, *p_x1, *p_xln2;
    cudaGetSymbolAddress((void**)&p_xln,  g_xln);
    cudaGetSymbolAddress((void**)&p_x1,   g_x1);
    cudaGetSymbolAddress((void**)&p_xln2, g_xln2);

    const int pass1_smem = (2 * 64 * 68 + 64 * 72) * 4;
    const int pass2_smem = (3 * 64 * 68 + 64 * 72 + 128) * 4;
    cudaFuncSetAttribute(attn_pass1, cudaFuncAttributeMaxDynamicSharedMemorySize, pass1_smem);
    cudaFuncSetAttribute(attn_pass2, cudaFuncAttributeMaxDynamicSharedMemorySize, pass2_smem);

    ln_kernel<<<NTOK / 8, 256>>>(x, g1, b1, p_xln, 1);
    gemm_tf32<0><<<dim3(26, NTOK / 128, 1), 256>>>(Wq, Wk, Wr);   // Q, K, router fused
    router_argmax<<<(NTOK * H_ + 255) / 256, 256>>>();
    vsel_kernel<<<NTOK / 2, 384>>>(Wv);
    attn_pass1<<<dim3(S_ / 64, H_, B_), 256, pass1_smem>>>();
    attn_pass2<<<dim3(S_ / 64, H_, B_), 256, pass2_smem>>>();
    osel_kernel<<<NTOK / 2, 384>>>(Wo, x);
    ln_kernel<<<NTOK / 8, 256>>>(p_x1, g2, b2, p_xln2, 0);
    gate_kernel<<<NTOK / 8, 256>>>(gff);
    capacity_kernel<<<1, 256>>>();
    gemm_tf32<1><<<dim3(DFF_ / 64, (CAP_ + 127) / 128, E_), 256>>>(W1, nullptr, nullptr);
    gemm_tf32<2><<<dim3(D_ / 64, (CAP_ + 127) / 128, E_), 256>>>(W2, nullptr, nullptr);
    combine_kernel<<<NTOK / 8, 256>>>(out);
    if (out_size > NOUT) aux_kernel<<<1, 256>>>(out, out_size);
}

// round 12
// speedup vs baseline: 1.5184x; 1.0319x over previous
#include <cuda_runtime.h>
#include <math.h>

#define B_ 2
#define S_ 1024
#define D_ 768
#define H_ 12
#define E_ 8
#define DH_ 64
#define DFF_ 2048
#define NTOK (B_*S_)
#define CAP_ 320
#define NOUT (NTOK*D_)

// ---------------- scratch (device globals; no allocation allowed) -------------
__device__ float g_xln [NTOK*D_];
__device__ float g_q   [NTOK*D_];
__device__ float g_k   [NTOK*D_];
__device__ float g_vsel[NTOK*D_];
__device__ float g_attn[NTOK*D_];
__device__ float g_x1  [NTOK*D_];
__device__ float g_xln2[NTOK*D_];
__device__ float g_rlog[NTOK*(H_*E_)];
__device__ int   g_eidx[NTOK*H_];
__device__ int   g_hard[H_*E_];
__device__ float g_m[B_*H_*S_];
__device__ float g_l[B_*H_*S_];
__device__ int   g_tk_idx[NTOK*2];
__device__ float g_tk_prob[NTOK*2];
__device__ int   g_token_slot[NTOK*2];
__device__ int   g_slot_token[E_*CAP_];
__device__ float g_slot_w[E_*CAP_];
__device__ int   g_ecount[E_];
__device__ float g_hbuf[E_*CAP_*DFF_];
__device__ float g_sout[E_*CAP_*D_];

// ---------------- tf32 tensor-core helpers -------------------------------------
__device__ __forceinline__ unsigned to_tf32(float f) {
    unsigned u; asm("cvt.rna.tf32.f32 %0,%1;" : "=r"(u) : "f"(f)); return u;
}
__device__ __forceinline__ void mma_tf32(float c[4], const unsigned a[4], const unsigned b[2]) {
    asm("mma.sync.aligned.m16n8k8.row.col.f32.tf32.tf32.f32 "
        "{%0,%1,%2,%3},{%4,%5,%6,%7},{%8,%9},{%0,%1,%2,%3};"
        : "+f"(c[0]), "+f"(c[1]), "+f"(c[2]), "+f"(c[3])
        : "r"(a[0]), "r"(a[1]), "r"(a[2]), "r"(a[3]), "r"(b[0]), "r"(b[1]));
}
__device__ __forceinline__ void cp16(void* smem, const void* g) {
    unsigned saddr = (unsigned)__cvta_generic_to_shared(smem);
    asm volatile("cp.async.cg.shared.global [%0], [%1], 16;" :: "r"(saddr), "l"(g));
}
#define CP_COMMIT() asm volatile("cp.async.commit_group;" ::: "memory")
#define CP_WAIT0()  asm volatile("cp.async.wait_group 0;" ::: "memory")

// ---------------- LayerNorm (warp per row, float4); optional g_hard clear ------
__global__ void ln_kernel(const float* __restrict__ x, const float* __restrict__ g,
                          const float* __restrict__ b, float* __restrict__ out,
                          int clear_hard) {
    if (clear_hard && blockIdx.x == 0 && threadIdx.x < H_ * E_) g_hard[threadIdx.x] = 0;
    int wid = threadIdx.x >> 5, lane = threadIdx.x & 31;
    int row = blockIdx.x * 8 + wid;
    const float4* xr = (const float4*)(x + (size_t)row * D_);
    float4 v[6];
    float s = 0.f, s2 = 0.f;
#pragma unroll
    for (int i = 0; i < 6; i++) {
        v[i] = xr[lane + i * 32];
        s  += v[i].x + v[i].y + v[i].z + v[i].w;
        s2 += v[i].x * v[i].x + v[i].y * v[i].y + v[i].z * v[i].z + v[i].w * v[i].w;
    }
#pragma unroll
    for (int o = 16; o > 0; o >>= 1) {
        s  += __shfl_xor_sync(0xffffffffu, s,  o);
        s2 += __shfl_xor_sync(0xffffffffu, s2, o);
    }
    float mean = s * (1.f / D_);
    float inv  = rsqrtf(s2 * (1.f / D_) - mean * mean + 1e-5f);
    float4* orow = (float4*)(out + (size_t)row * D_);
    const float4* g4 = (const float4*)g;
    const float4* b4 = (const float4*)b;
#pragma unroll
    for (int i = 0; i < 6; i++) {
        float4 gg = g4[lane + i * 32], bb = b4[lane + i * 32];
        float4 o;
        o.x = (v[i].x - mean) * inv * gg.x + bb.x;
        o.y = (v[i].y - mean) * inv * gg.y + bb.y;
        o.z = (v[i].z - mean) * inv * gg.z + bb.z;
        o.w = (v[i].w - mean) * inv * gg.w + bb.w;
        orow[lane + i * 32] = o;
    }
}

// ---------------- tf32 GEMM, 128x64x16 tiles, cp.async double buffered ---------
// Operands staged as RAW fp32 bits (tf32 truncation semantics).
// MODE 0: fused QKR. bx<12: Wq->g_q | bx<24: Wk->g_k | bx>=24: Wr->g_rlog (N=96)
// MODE 1: FFN GEMM1 (gathered A rows, ReLU). z=e. B=W1[e]. C=g_hbuf[e].
// MODE 2: FFN GEMM2 (slot-weight scale).     z=e. B=W2[e]. C=g_sout[e].
#define ASTRIDE 20
#define BSTRIDE 72
template<int MODE>
__global__ __launch_bounds__(256)
void gemm_tf32(const float* __restrict__ P0, const float* __restrict__ P1,
               const float* __restrict__ P2) {
    __shared__ __align__(16) unsigned As[2][128 * ASTRIDE];
    __shared__ __align__(16) unsigned Bs[2][16 * BSTRIDE];

    const int tid = threadIdx.x, wid = tid >> 5, lane = tid & 31;
    const int e  = blockIdx.z;
    const int m0 = blockIdx.y * 128;

    int N, K, count, n0;
    const float* Bm;
    float* C;
    const float* Abase;
    if (MODE == 0) {
        K = D_; count = NTOK; Abase = g_xln;
        int bx = blockIdx.x;
        if (bx < 12)      { Bm = P0; C = g_q;    N = D_; n0 = bx * 64; }
        else if (bx < 24) { Bm = P1; C = g_k;    N = D_; n0 = (bx - 12) * 64; }
        else              { Bm = P2; C = g_rlog; N = 96; n0 = (bx - 24) * 64; }
    } else if (MODE == 1) {
        N = DFF_; K = D_; count = g_ecount[e]; n0 = blockIdx.x * 64;
        if (count <= 0 || m0 >= count) return;
        Bm = P0 + (size_t)e * D_ * DFF_;
        C  = g_hbuf + (size_t)e * CAP_ * DFF_;
        Abase = g_xln2;
    } else {
        N = D_; K = DFF_; count = g_ecount[e]; n0 = blockIdx.x * 64;
        if (count <= 0 || m0 >= count) return;
        Bm = P0 + (size_t)e * DFF_ * D_;
        C  = g_sout + (size_t)e * CAP_ * D_;
        Abase = g_hbuf + (size_t)e * CAP_ * DFF_;
    }

    const int sm_r = tid >> 1;
    const int sm_k = (tid & 1) * 8;
    const int brow = tid >> 4;
    const int bcol = (tid & 15) * 4;

    const float* Aptr;
    {
        int r = m0 + sm_r;
        if (r >= count) r = count - 1;
        if (MODE == 1)
            Aptr = Abase + (size_t)g_slot_token[e * CAP_ + r] * D_ + sm_k;
        else
            Aptr = Abase + (size_t)r * K + sm_k;
    }
    int bc_eff = bcol;
    if (n0 + bcol + 4 > N) bc_eff = N - 4 - n0;
    const float* Bptr = Bm + (size_t)brow * N + n0 + bc_eff;

    const int wm0 = (wid & 3) * 32;
    const int wn0 = (wid >> 2) * 32;
    const int gr = lane >> 2, gc = lane & 3;

    float acc[2][4][4];
#pragma unroll
    for (int i = 0; i < 2; i++)
#pragma unroll
        for (int j = 0; j < 4; j++)
#pragma unroll
            for (int q = 0; q < 4; q++) acc[i][j][q] = 0.f;

    const int nk = K / 16;

    // preload tile 0 -> buffer 0 (async, no register round-trip)
    cp16(&As[0][sm_r * ASTRIDE + sm_k],     Aptr);
    cp16(&As[0][sm_r * ASTRIDE + sm_k + 4], Aptr + 4);
    cp16(&Bs[0][brow * BSTRIDE + bcol],     Bptr);
    CP_COMMIT();

    for (int kb = 0; kb < nk; kb++) {
        const int buf = kb & 1;
        CP_WAIT0();           // tile kb resident
        __syncthreads();      // also guarantees prior reads of buf^1 are done
        if (kb + 1 < nk) {    // prefetch tile kb+1 overlapped with MMA below
            cp16(&As[buf ^ 1][sm_r * ASTRIDE + sm_k],     Aptr + (kb + 1) * 16);
            cp16(&As[buf ^ 1][sm_r * ASTRIDE + sm_k + 4], Aptr + (kb + 1) * 16 + 4);
            cp16(&Bs[buf ^ 1][brow * BSTRIDE + bcol],     Bptr + (size_t)(kb + 1) * 16 * N);
            CP_COMMIT();
        }
        const unsigned* Ab = As[buf];
        const unsigned* Bb = Bs[buf];
#pragma unroll
        for (int kk = 0; kk < 16; kk += 8) {
            unsigned a[2][4];
#pragma unroll
            for (int mf = 0; mf < 2; mf++) {
                int mb = wm0 + mf * 16;
                a[mf][0] = Ab[(mb + gr)     * ASTRIDE + kk + gc];
                a[mf][1] = Ab[(mb + gr + 8) * ASTRIDE + kk + gc];
                a[mf][2] = Ab[(mb + gr)     * ASTRIDE + kk + gc + 4];
                a[mf][3] = Ab[(mb + gr + 8) * ASTRIDE + kk + gc + 4];
            }
#pragma unroll
            for (int nf = 0; nf < 4; nf++) {
                int nb = wn0 + nf * 8 + gr;
                unsigned b[2];
                b[0] = Bb[(kk + gc)     * BSTRIDE + nb];
                b[1] = Bb[(kk + gc + 4) * BSTRIDE + nb];
                mma_tf32(acc[0][nf], a[0], b);
                mma_tf32(acc[1][nf], a[1], b);
            }
        }
    }

#pragma unroll
    for (int mf = 0; mf < 2; mf++) {
        int rbase = m0 + wm0 + mf * 16 + gr;
#pragma unroll
        for (int half = 0; half < 2; half++) {
            int r = rbase + half * 8;
            if (MODE != 0 && r >= count) continue;
            float w = 1.f;
            if (MODE == 2) w = g_slot_w[e * CAP_ + r];
#pragma unroll
            for (int nf = 0; nf < 4; nf++) {
                int cc = n0 + wn0 + nf * 8 + gc * 2;
                if (MODE == 0 && cc + 2 > N) continue;
                float v0 = acc[mf][nf][half * 2 + 0];
                float v1 = acc[mf][nf][half * 2 + 1];
                if (MODE == 1) { v0 = fmaxf(v0, 0.f); v1 = fmaxf(v1, 0.f); }
                else if (MODE == 2) { v0 *= w; v1 *= w; }
                *(float2*)(C + (size_t)r * N + cc) = make_float2(v0, v1);
            }
        }
    }
}

__global__ void router_argmax() {
    int idx = blockIdx.x * 256 + threadIdx.x;
    if (idx >= NTOK * H_) return;
    int row = idx / H_, h = idx - row * H_;
    const float* lg = g_rlog + (size_t)row * 96 + h * 8;
    float best = lg[0]; int bi = 0;
#pragma unroll
    for (int e = 1; e < E_; e++) { float v = lg[e]; if (v > best) { best = v; bi = e; } }
    g_eidx[row * H_ + h] = bi;
    atomicAdd(&g_hard[h * E_ + bi], 1);
}

// ---------------- per (token, head) expert matvecs — 2 tokens per block --------
__global__ void vsel_kernel(const float* __restrict__ Wv) {
    int row0 = blockIdx.x * 2, tid = threadIdx.x;
    int h = tid >> 5, lane = tid & 31;
    int e0 = g_eidx[row0 * H_ + h];
    int e1 = g_eidx[(row0 + 1) * H_ + h];
    const float* wv0 = Wv + (size_t)(h * E_ + e0) * DH_ * DH_;
    const float* wv1 = Wv + (size_t)(h * E_ + e1) * DH_ * DH_;
    const float* x0 = g_xln + (size_t)row0 * D_ + h * DH_;
    const float* x1 = x0 + D_;
    float a0 = 0.f, b0 = 0.f, a1 = 0.f, b1 = 0.f;
    if (e0 == e1) {
#pragma unroll 4
        for (int d = 0; d < DH_; d++) {
            float wA = wv0[d * DH_ + lane], wB = wv0[d * DH_ + lane + 32];
            float v0 = x0[d], v1 = x1[d];
            a0 += v0 * wA; b0 += v0 * wB;
            a1 += v1 * wA; b1 += v1 * wB;
        }
    } else {
#pragma unroll 4
        for (int d = 0; d < DH_; d++) {
            float v0 = x0[d], v1 = x1[d];
            a0 += v0 * wv0[d * DH_ + lane];
            b0 += v0 * wv0[d * DH_ + lane + 32];
            a1 += v1 * wv1[d * DH_ + lane];
            b1 += v1 * wv1[d * DH_ + lane + 32];
        }
    }
    size_t o = (size_t)row0 * D_ + h * DH_ + lane;
    g_vsel[o]           = a0; g_vsel[o + 32]      = b0;
    g_vsel[o + D_]      = a1; g_vsel[o + D_ + 32] = b1;
}

__global__ void osel_kernel(const float* __restrict__ Wo, const float* __restrict__ x) {
    int row0 = blockIdx.x * 2, tid = threadIdx.x;
    int h = tid >> 5, lane = tid & 31;
    int e0 = g_eidx[row0 * H_ + h];
    int e1 = g_eidx[(row0 + 1) * H_ + h];
    const float* wo0 = Wo + (size_t)(h * E_ + e0) * DH_ * DH_;
    const float* wo1 = Wo + (size_t)(h * E_ + e1) * DH_ * DH_;
    const float* a0p = g_attn + (size_t)row0 * D_ + h * DH_;
    const float* a1p = a0p + D_;
    float a0 = 0.f, b0 = 0.f, a1 = 0.f, b1 = 0.f;
    if (e0 == e1) {
#pragma unroll 4
        for (int f = 0; f < DH_; f++) {
            float wA = wo0[f * DH_ + lane], wB = wo0[f * DH_ + lane + 32];
            float v0 = a0p[f], v1 = a1p[f];
            a0 += v0 * wA; b0 += v0 * wB;
            a1 += v1 * wA; b1 += v1 * wB;
        }
    } else {
#pragma unroll 4
        for (int f = 0; f < DH_; f++) {
            float v0 = a0p[f], v1 = a1p[f];
            a0 += v0 * wo0[f * DH_ + lane];
            b0 += v0 * wo0[f * DH_ + lane + 32];
            a1 += v1 * wo1[f * DH_ + lane];
            b1 += v1 * wo1[f * DH_ + lane + 32];
        }
    }
    size_t o = (size_t)row0 * D_ + h * DH_ + lane;
    g_x1[o]           = x[o]           + a0;
    g_x1[o + 32]      = x[o + 32]      + b0;
    g_x1[o + D_]      = x[o + D_]      + a1;
    g_x1[o + D_ + 32] = x[o + D_ + 32] + b1;
}

// ---------------- attention pass 1 (tf32 MMA): row stats m_s, l_s --------------
__global__ __launch_bounds__(256)
void attn_pass1() {
    extern __shared__ unsigned dsp[];
    unsigned* uQ = dsp;
    unsigned* uK = dsp + 64 * 68;
    float* Ss = (float*)(dsp + 2 * 64 * 68);
    int s0 = blockIdx.x * 64, h = blockIdx.y, b = blockIdx.z;
    int tid = threadIdx.x, wid = tid >> 5, lane = tid & 31;
    int gr = lane >> 2, gc = lane & 3;
    const float* qb = g_q + (size_t)b * S_ * D_ + h * DH_;
    const float* kb = g_k + (size_t)b * S_ * D_ + h * DH_;
    {
        int r = tid >> 2, dg = (tid & 3) * 16;
        const float* src = qb + (size_t)(s0 + r) * D_ + dg;
#pragma unroll
        for (int i = 0; i < 4; i++) {
            float4 v = *(const float4*)(src + i * 4);
            uQ[r * 68 + dg + i * 4 + 0] = to_tf32(v.x);
            uQ[r * 68 + dg + i * 4 + 1] = to_tf32(v.y);
            uQ[r * 68 + dg + i * 4 + 2] = to_tf32(v.z);
            uQ[r * 68 + dg + i * 4 + 3] = to_tf32(v.w);
        }
    }
    const int wm0 = (wid & 1) * 32, wn0 = (wid >> 1) * 16;
    const int rr = tid >> 2, qq = tid & 3;
    float run_m = -INFINITY, run_l = 0.f;

    for (int t0 = 0; t0 <= s0; t0 += 64) {
        {
            int r = tid >> 2, dg = (tid & 3) * 16;
            const float* src = kb + (size_t)(t0 + r) * D_ + dg;
#pragma unroll
            for (int i = 0; i < 4; i++) {
                float4 v = *(const float4*)(src + i * 4);
                uK[(dg + i * 4 + 0) * 68 + r] = to_tf32(v.x);
                uK[(dg + i * 4 + 1) * 68 + r] = to_tf32(v.y);
                uK[(dg + i * 4 + 2) * 68 + r] = to_tf32(v.z);
                uK[(dg + i * 4 + 3) * 68 + r] = to_tf32(v.w);
            }
        }
        __syncthreads();
        float c[2][2][4];
#pragma unroll
        for (int mf = 0; mf < 2; mf++)
#pragma unroll
            for (int nf = 0; nf < 2; nf++)
#pragma unroll
                for (int q = 0; q < 4; q++) c[mf][nf][q] = 0.f;
#pragma unroll
        for (int kk = 0; kk < 64; kk += 8) {
            unsigned a[2][4], bf[2][2];
#pragma unroll
            for (int mf = 0; mf < 2; mf++) {
                int mb = wm0 + mf * 16;
                a[mf][0] = uQ[(mb + gr)     * 68 + kk + gc];
                a[mf][1] = uQ[(mb + gr + 8) * 68 + kk + gc];
                a[mf][2] = uQ[(mb + gr)     * 68 + kk + gc + 4];
                a[mf][3] = uQ[(mb + gr + 8) * 68 + kk + gc + 4];
            }
#pragma unroll
            for (int nf = 0; nf < 2; nf++) {
                int nb = wn0 + nf * 8 + gr;
                bf[nf][0] = uK[(kk + gc)     * 68 + nb];
                bf[nf][1] = uK[(kk + gc + 4) * 68 + nb];
            }
#pragma unroll
            for (int mf = 0; mf < 2; mf++)
#pragma unroll
                for (int nf = 0; nf < 2; nf++)
                    mma_tf32(c[mf][nf], a[mf], bf[nf]);
        }
#pragma unroll
        for (int mf = 0; mf < 2; mf++)
#pragma unroll
            for (int nf = 0; nf < 2; nf++) {
                int row = wm0 + mf * 16 + gr, col = wn0 + nf * 8 + 2 * gc;
                *(float2*)&Ss[row * 72 + col]       = make_float2(c[mf][nf][0], c[mf][nf][1]);
                *(float2*)&Ss[(row + 8) * 72 + col] = make_float2(c[mf][nf][2], c[mf][nf][3]);
            }
        __syncthreads();
        float v[16];
#pragma unroll
        for (int i = 0; i < 4; i++) {
            float4 t4 = *(const float4*)&Ss[rr * 72 + qq * 16 + i * 4];
            v[i * 4 + 0] = t4.x; v[i * 4 + 1] = t4.y; v[i * 4 + 2] = t4.z; v[i * 4 + 3] = t4.w;
        }
        int gs = s0 + rr;
        float mx = -INFINITY;
#pragma unroll
        for (int cI = 0; cI < 16; cI++) {
            int gt = t0 + qq * 16 + cI;
            if (gt <= gs) mx = fmaxf(mx, v[cI] * 0.125f);
        }
        mx = fmaxf(mx, __shfl_xor_sync(0xffffffffu, mx, 1));
        mx = fmaxf(mx, __shfl_xor_sync(0xffffffffu, mx, 2));
        float mn = fmaxf(run_m, mx);
        float alpha = __expf(run_m - mn);
        float sum = 0.f;
#pragma unroll
        for (int cI = 0; cI < 16; cI++) {
            int gt = t0 + qq * 16 + cI;
            if (gt <= gs) sum += __expf(v[cI] * 0.125f - mn);
        }
        sum += __shfl_xor_sync(0xffffffffu, sum, 1);
        sum += __shfl_xor_sync(0xffffffffu, sum, 2);
        run_l = run_l * alpha + sum;
        run_m = mn;
    }
    if (qq == 0) {
        int o = (b * H_ + h) * S_ + s0 + rr;
        g_m[o] = run_m; g_l[o] = run_l;
    }
}

// ---------------- attention pass 2 (tf32 MMA): out[t] = sum_s P[s,t] v[s] ------
__global__ __launch_bounds__(256)
void attn_pass2() {
    extern __shared__ unsigned dsp2[];
    unsigned* uK = dsp2;
    unsigned* uQ = dsp2 + 4352;
    unsigned* uV = dsp2 + 8704;
    unsigned* uP = dsp2 + 13056;
    float* srm  = (float*)(dsp2 + 17664);
    float* sinv = srm + 64;
    int t0 = blockIdx.x * 64, h = blockIdx.y, b = blockIdx.z;
    int tid = threadIdx.x, wid = tid >> 5, lane = tid & 31;
    int gr = lane >> 2, gc = lane & 3;
    const float* qb = g_q    + (size_t)b * S_ * D_ + h * DH_;
    const float* kb = g_k    + (size_t)b * S_ * D_ + h * DH_;
    const float* vb = g_vsel + (size_t)b * S_ * D_ + h * DH_;
    {
        int r = tid >> 2, dg = (tid & 3) * 16;
        const float* src = kb + (size_t)(t0 + r) * D_ + dg;
#pragma unroll
        for (int i = 0; i < 4; i++) {
            float4 v = *(const float4*)(src + i * 4);
            uK[(dg + i * 4 + 0) * 68 + r] = to_tf32(v.x);
            uK[(dg + i * 4 + 1) * 68 + r] = to_tf32(v.y);
            uK[(dg + i * 4 + 2) * 68 + r] = to_tf32(v.z);
            uK[(dg + i * 4 + 3) * 68 + r] = to_tf32(v.w);
        }
    }
    const int wm0 = (wid & 1) * 32, wn0 = (wid >> 1) * 16;
    float O[2][2][4];
#pragma unroll
    for (int mf = 0; mf < 2; mf++)
#pragma unroll
        for (int nf = 0; nf < 2; nf++)
#pragma unroll
            for (int q = 0; q < 4; q++) O[mf][nf][q] = 0.f;

    for (int st0 = t0; st0 < S_; st0 += 64) {
        {
            int r = tid >> 2, dg = (tid & 3) * 16;
            const float* qsrc = qb + (size_t)(st0 + r) * D_ + dg;
            const float* vsrc = vb + (size_t)(st0 + r) * D_ + dg;
#pragma unroll
            for (int i = 0; i < 4; i++) {
                float4 v = *(const float4*)(qsrc + i * 4);
                uQ[r * 68 + dg + i * 4 + 0] = to_tf32(v.x);
                uQ[r * 68 + dg + i * 4 + 1] = to_tf32(v.y);
                uQ[r * 68 + dg + i * 4 + 2] = to_tf32(v.z);
                uQ[r * 68 + dg + i * 4 + 3] = to_tf32(v.w);
                float4 w = *(const float4*)(vsrc + i * 4);
                uV[r * 68 + dg + i * 4 + 0] = to_tf32(w.x);
                uV[r * 68 + dg + i * 4 + 1] = to_tf32(w.y);
                uV[r * 68 + dg + i * 4 + 2] = to_tf32(w.z);
                uV[r * 68 + dg + i * 4 + 3] = to_tf32(w.w);
            }
        }
        if (tid < 64) {
            int o = (b * H_ + h) * S_ + st0 + tid;
            srm[tid] = g_m[o]; sinv[tid] = 1.f / g_l[o];
        }
        __syncthreads();
        float c[2][2][4];
#pragma unroll
        for (int mf = 0; mf < 2; mf++)
#pragma unroll
            for (int nf = 0; nf < 2; nf++)
#pragma unroll
                for (int q = 0; q < 4; q++) c[mf][nf][q] = 0.f;
#pragma unroll
        for (int kk = 0; kk < 64; kk += 8) {
            unsigned a[2][4], bf[2][2];
#pragma unroll
            for (int mf = 0; mf < 2; mf++) {
                int mb = wm0 + mf * 16;
                a[mf][0] = uQ[(mb + gr)     * 68 + kk + gc];
                a[mf][1] = uQ[(mb + gr + 8) * 68 + kk + gc];
                a[mf][2] = uQ[(mb + gr)     * 68 + kk + gc + 4];
                a[mf][3] = uQ[(mb + gr + 8) * 68 + kk + gc + 4];
            }
#pragma unroll
            for (int nf = 0; nf < 2; nf++) {
                int nb = wn0 + nf * 8 + gr;
                bf[nf][0] = uK[(kk + gc)     * 68 + nb];
                bf[nf][1] = uK[(kk + gc + 4) * 68 + nb];
            }
#pragma unroll
            for (int mf = 0; mf < 2; mf++)
#pragma unroll
                for (int nf = 0; nf < 2; nf++)
                    mma_tf32(c[mf][nf], a[mf], bf[nf]);
        }
#pragma unroll
        for (int mf = 0; mf < 2; mf++) {
            int sl_a = wm0 + mf * 16 + gr;
            int sl_b = sl_a + 8;
            int gs_a = st0 + sl_a, gs_b = st0 + sl_b;
            float ma = srm[sl_a], ia = sinv[sl_a];
            float mb2 = srm[sl_b], ib = sinv[sl_b];
#pragma unroll
            for (int nf = 0; nf < 2; nf++) {
                int tc = wn0 + nf * 8 + 2 * gc;
                int gt0 = t0 + tc, gt1 = gt0 + 1;
                float p;
                p = (gt0 <= gs_a) ? __expf(c[mf][nf][0] * 0.125f - ma) * ia : 0.f;
                uP[tc * 72 + sl_a] = to_tf32(p);
                p = (gt1 <= gs_a) ? __expf(c[mf][nf][1] * 0.125f - ma) * ia : 0.f;
                uP[(tc + 1) * 72 + sl_a] = to_tf32(p);
                p = (gt0 <= gs_b) ? __expf(c[mf][nf][2] * 0.125f - mb2) * ib : 0.f;
                uP[tc * 72 + sl_b] = to_tf32(p);
                p = (gt1 <= gs_b) ? __expf(c[mf][nf][3] * 0.125f - mb2) * ib : 0.f;
                uP[(tc + 1) * 72 + sl_b] = to_tf32(p);
            }
        }
        __syncthreads();
#pragma unroll
        for (int kk = 0; kk < 64; kk += 8) {
            unsigned a[2][4], bf[2][2];
#pragma unroll
            for (int mf = 0; mf < 2; mf++) {
                int mb = wm0 + mf * 16;
                a[mf][0] = uP[(mb + gr)     * 72 + kk + gc];
                a[mf][1] = uP[(mb + gr + 8) * 72 + kk + gc];
                a[mf][2] = uP[(mb + gr)     * 72 + kk + gc + 4];
                a[mf][3] = uP[(mb + gr + 8) * 72 + kk + gc + 4];
            }
#pragma unroll
            for (int nf = 0; nf < 2; nf++) {
                int nb = wn0 + nf * 8 + gr;
                bf[nf][0] = uV[(kk + gc)     * 68 + nb];
                bf[nf][1] = uV[(kk + gc + 4) * 68 + nb];
            }
#pragma unroll
            for (int mf = 0; mf < 2; mf++)
#pragma unroll
                for (int nf = 0; nf < 2; nf++)
                    mma_tf32(O[mf][nf], a[mf], bf[nf]);
        }
        __syncthreads();
    }
#pragma unroll
    for (int mf = 0; mf < 2; mf++) {
        int trow = t0 + wm0 + mf * 16 + gr;
#pragma unroll
        for (int nf = 0; nf < 2; nf++) {
            int fc = wn0 + nf * 8 + 2 * gc;
            *(float2*)(g_attn + (size_t)(b * S_ + trow) * D_ + h * DH_ + fc)
                = make_float2(O[mf][nf][0], O[mf][nf][1]);
            *(float2*)(g_attn + (size_t)(b * S_ + trow + 8) * D_ + h * DH_ + fc)
                = make_float2(O[mf][nf][2], O[mf][nf][3]);
        }
    }
}

// ---------------- FFN gate + top-2 (warp per token) ----------------------------
__global__ void gate_kernel(const float* __restrict__ gff) {
    int wid = threadIdx.x >> 5, lane = threadIdx.x & 31;
    int row = blockIdx.x * 8 + wid;
    const float* xr = g_xln2 + (size_t)row * D_;
    float acc[8] = {};
    for (int d = lane; d < D_; d += 32) {
        float xv = xr[d];
        float4 gA = *(const float4*)(gff + (size_t)d * E_);
        float4 gB = *(const float4*)(gff + (size_t)d * E_ + 4);
        acc[0] += xv * gA.x; acc[1] += xv * gA.y; acc[2] += xv * gA.z; acc[3] += xv * gA.w;
        acc[4] += xv * gB.x; acc[5] += xv * gB.y; acc[6] += xv * gB.z; acc[7] += xv * gB.w;
    }
#pragma unroll
    for (int off = 16; off > 0; off >>= 1)
#pragma unroll
        for (int i = 0; i < 8; i++)
            acc[i] += __shfl_down_sync(0xffffffffu, acc[i], off);
    if (lane == 0) {
        int i0 = 0; float v0 = acc[0];
#pragma unroll
        for (int e = 1; e < E_; e++) if (acc[e] > v0) { v0 = acc[e]; i0 = e; }
        int i1 = -1; float v1 = -3.4e38f;
#pragma unroll
        for (int e = 0; e < E_; e++) { if (e == i0) continue; if (acc[e] > v1) { v1 = acc[e]; i1 = e; } }
        float e1 = expf(v1 - v0);
        float z = 1.f + e1;
        g_tk_idx[row * 2] = i0; g_tk_idx[row * 2 + 1] = i1;
        g_tk_prob[row * 2] = 1.f / z; g_tk_prob[row * 2 + 1] = e1 / z;
    }
}

// ---------------- capacity + deterministic slot assignment --------------------
__global__ void capacity_kernel() {
    int tid = threadIdx.x; // 256 = 8 warps, warp per expert
    int w = tid >> 5, lane = tid & 31;
    if (w < E_) {
        int e = w, c = 0;
        for (int i0 = 0; i0 < NTOK * 2; i0 += 32) {
            int i = i0 + lane;
            int idx = g_tk_idx[i];
            bool match = (idx == e);
            unsigned msk = __ballot_sync(0xffffffffu, match);
            if (match) {
                int rank = c + __popc(msk & ((1u << lane) - 1u));
                if (rank < CAP_) {
                    g_slot_token[e * CAP_ + rank] = i >> 1;
                    g_token_slot[i] = e * CAP_ + rank;
                } else {
                    g_token_slot[i] = -1;
                }
            }
            c += __popc(msk);
        }
        if (lane == 0) g_ecount[e] = (c < CAP_) ? c : CAP_;
    }
    __syncthreads();
    for (int t = tid; t < NTOK; t += 256) {
        int s0 = g_token_slot[2 * t], s1 = g_token_slot[2 * t + 1];
        float p0 = (s0 >= 0) ? g_tk_prob[2 * t]     : 0.f;
        float p1 = (s1 >= 0) ? g_tk_prob[2 * t + 1] : 0.f;
        float inv = 1.f / (p0 + p1 + 1e-9f);
        if (s0 >= 0) g_slot_w[s0] = p0 * inv;
        if (s1 >= 0) g_slot_w[s1] = p1 * inv;
    }
}

// ---------------- combine: out = x1 + f (warp per row, float4) -----------------
__global__ void combine_kernel(float* __restrict__ out) {
    int wid = threadIdx.x >> 5, lane = threadIdx.x & 31;
    int row = blockIdx.x * 8 + wid;
    int s0 = g_token_slot[2 * row], s1 = g_token_slot[2 * row + 1];
    const float4* xr = (const float4*)(g_x1 + (size_t)row * D_);
    const float4* f0 = (s0 >= 0) ? (const float4*)(g_sout + (size_t)s0 * D_) : nullptr;
    const float4* f1 = (s1 >= 0) ? (const float4*)(g_sout + (size_t)s1 * D_) : nullptr;
    float4* orow = (float4*)(out + (size_t)row * D_);
#pragma unroll
    for (int i = 0; i < 6; i++) {
        int c = lane + i * 32;
        float4 v = xr[c];
        if (f0) { float4 a = f0[c]; v.x += a.x; v.y += a.y; v.z += a.z; v.w += a.w; }
        if (f1) { float4 a = f1[c]; v.x += a.x; v.y += a.y; v.z += a.z; v.w += a.w; }
        orow[c] = v;
    }
}

// ---------------- aux losses (parallelized) ------------------------------------
__global__ void aux_kernel(float* __restrict__ out, int out_size) {
    __shared__ float ic_sh[E_];
    __shared__ float sa;
    int tid = threadIdx.x, w = tid >> 5, lane = tid & 31;
    if (w < E_) {
        int c = g_ecount[w];
        float s = 0.f;
        for (int r = lane; r < c; r += 32) s += g_slot_w[w * CAP_ + r];
#pragma unroll
        for (int o = 16; o > 0; o >>= 1) s += __shfl_down_sync(0xffffffffu, s, o);
        if (lane == 0) ic_sh[w] = s;
    }
    __syncthreads();
    if (tid == 0) {
        const float scale = 0.01f / 2048.f;
        float es = 0.f;
        for (int i = 0; i < H_ * E_; i++) es += g_hard[i] * scale;
        float a1 = 0.f;
        for (int i = 0; i < H_ * E_; i++) {
            float p = (g_hard[i] * scale) / (es + 1e-9f);
            a1 += p * p;
        }
        a1 *= (float)(E_ * H_);
        float tcs = 0.f, ics = 0.f;
        for (int e = 0; e < E_; e++) { tcs += (float)g_ecount[e]; ics += ic_sh[e]; }
        float a2 = 0.f;
        for (int e = 0; e < E_; e++) a2 += ((float)g_ecount[e] / tcs) * (ic_sh[e] / ics);
        a2 *= (float)E_;
        sa = a1 + a2;
    }
    __syncthreads();
    for (int i = NOUT + tid; i < out_size; i += blockDim.x) out[i] = sa;
}

// ---------------- launch -------------------------------------------------------
extern "C" void kernel_launch(void* const* d_in, const int* in_sizes, int n_in,
                              void* d_out, int out_size) {
    const float* x   = (const float*)d_in[0];
    // d_in[1] = mask (pure causal 0/-1e9, applied analytically)
    const float* Wq  = (const float*)d_in[2];
    const float* Wk  = (const float*)d_in[3];
    const float* Wv  = (const float*)d_in[4];
    const float* Wo  = (const float*)d_in[5];
    const float* Wr  = (const float*)d_in[6];
    const float* g1  = (const float*)d_in[7];
    const float* b1  = (const float*)d_in[8];
    const float* g2  = (const float*)d_in[9];
    const float* b2  = (const float*)d_in[10];
    const float* gff = (const float*)d_in[11];
    const float* W1  = (const float*)d_in[12];
    const float* W2  = (const float*)d_in[13];
    float* out = (float*)d_out;

    float *p_xln, *p_x1, *p_xln2;
    cudaGetSymbolAddress((void**)&p_xln,  g_xln);
    cudaGetSymbolAddress((void**)&p_x1,   g_x1);
    cudaGetSymbolAddress((void**)&p_xln2, g_xln2);

    const int pass1_smem = (2 * 64 * 68 + 64 * 72) * 4;
    const int pass2_smem = (3 * 64 * 68 + 64 * 72 + 128) * 4;
    cudaFuncSetAttribute(attn_pass1, cudaFuncAttributeMaxDynamicSharedMemorySize, pass1_smem);
    cudaFuncSetAttribute(attn_pass2, cudaFuncAttributeMaxDynamicSharedMemorySize, pass2_smem);

    ln_kernel<<<NTOK / 8, 256>>>(x, g1, b1, p_xln, 1);
    gemm_tf32<0><<<dim3(26, NTOK / 128, 1), 256>>>(Wq, Wk, Wr);   // Q, K, router fused
    router_argmax<<<(NTOK * H_ + 255) / 256, 256>>>();
    vsel_kernel<<<NTOK / 2, 384>>>(Wv);
    attn_pass1<<<dim3(S_ / 64, H_, B_), 256, pass1_smem>>>();
    attn_pass2<<<dim3(S_ / 64, H_, B_), 256, pass2_smem>>>();
    osel_kernel<<<NTOK / 2, 384>>>(Wo, x);
    ln_kernel<<<NTOK / 8, 256>>>(p_x1, g2, b2, p_xln2, 0);
    gate_kernel<<<NTOK / 8, 256>>>(gff);
    capacity_kernel<<<1, 256>>>();
    gemm_tf32<1><<<dim3(DFF_ / 64, (CAP_ + 127) / 128, E_), 256>>>(W1, nullptr, nullptr);
    gemm_tf32<2><<<dim3(D_ / 64, (CAP_ + 127) / 128, E_), 256>>>(W2, nullptr, nullptr);
    combine_kernel<<<NTOK / 8, 256>>>(out);
    if (out_size > NOUT) aux_kernel<<<1, 256>>>(out, out_size);
}

// round 13
// speedup vs baseline: 1.5894x; 1.0468x over previous
#include <cuda_runtime.h>
#include <math.h>

#define B_ 2
#define S_ 1024
#define D_ 768
#define H_ 12
#define E_ 8
#define DH_ 64
#define DFF_ 2048
#define NTOK (B_*S_)
#define CAP_ 320
#define NOUT (NTOK*D_)

// ---------------- scratch (device globals; no allocation allowed) -------------
__device__ float g_xln [NTOK*D_];
__device__ float g_q   [NTOK*D_];
__device__ float g_k   [NTOK*D_];
__device__ float g_vsel[NTOK*D_];
__device__ float g_attn[NTOK*D_];
__device__ float g_x1  [NTOK*D_];
__device__ float g_xln2[NTOK*D_];
__device__ float g_rlog[NTOK*(H_*E_)];
__device__ int   g_hcnt[H_*E_];            // per (h,e) token counts (== hard counts)
__device__ int   g_hlist[H_*E_*NTOK];      // per (h,e) token lists
__device__ float g_m[B_*H_*S_];
__device__ float g_l[B_*H_*S_];
__device__ int   g_tk_idx[NTOK*2];
__device__ float g_tk_prob[NTOK*2];
__device__ int   g_token_slot[NTOK*2];
__device__ int   g_slot_token[E_*CAP_];
__device__ float g_slot_w[E_*CAP_];
__device__ int   g_ecount[E_];
__device__ float g_hbuf[E_*CAP_*DFF_];
__device__ float g_sout[E_*CAP_*D_];

// ---------------- tf32 tensor-core helpers -------------------------------------
__device__ __forceinline__ unsigned to_tf32(float f) {
    unsigned u; asm("cvt.rna.tf32.f32 %0,%1;" : "=r"(u) : "f"(f)); return u;
}
__device__ __forceinline__ void mma_tf32(float c[4], const unsigned a[4], const unsigned b[2]) {
    asm("mma.sync.aligned.m16n8k8.row.col.f32.tf32.tf32.f32 "
        "{%0,%1,%2,%3},{%4,%5,%6,%7},{%8,%9},{%0,%1,%2,%3};"
        : "+f"(c[0]), "+f"(c[1]), "+f"(c[2]), "+f"(c[3])
        : "r"(a[0]), "r"(a[1]), "r"(a[2]), "r"(a[3]), "r"(b[0]), "r"(b[1]));
}
__device__ __forceinline__ void cp16(void* smem, const void* g) {
    unsigned saddr = (unsigned)__cvta_generic_to_shared(smem);
    asm volatile("cp.async.cg.shared.global [%0], [%1], 16;" :: "r"(saddr), "l"(g));
}
#define CP_COMMIT() asm volatile("cp.async.commit_group;" ::: "memory")
#define CP_WAIT0()  asm volatile("cp.async.wait_group 0;" ::: "memory")

// ---------------- LayerNorm (warp per row, float4); optional counter clear -----
__global__ void ln_kernel(const float* __restrict__ x, const float* __restrict__ g,
                          const float* __restrict__ b, float* __restrict__ out,
                          int clear_hard) {
    if (clear_hard && blockIdx.x == 0 && threadIdx.x < H_ * E_) g_hcnt[threadIdx.x] = 0;
    int wid = threadIdx.x >> 5, lane = threadIdx.x & 31;
    int row = blockIdx.x * 8 + wid;
    const float4* xr = (const float4*)(x + (size_t)row * D_);
    float4 v[6];
    float s = 0.f, s2 = 0.f;
#pragma unroll
    for (int i = 0; i < 6; i++) {
        v[i] = xr[lane + i * 32];
        s  += v[i].x + v[i].y + v[i].z + v[i].w;
        s2 += v[i].x * v[i].x + v[i].y * v[i].y + v[i].z * v[i].z + v[i].w * v[i].w;
    }
#pragma unroll
    for (int o = 16; o > 0; o >>= 1) {
        s  += __shfl_xor_sync(0xffffffffu, s,  o);
        s2 += __shfl_xor_sync(0xffffffffu, s2, o);
    }
    float mean = s * (1.f / D_);
    float inv  = rsqrtf(s2 * (1.f / D_) - mean * mean + 1e-5f);
    float4* orow = (float4*)(out + (size_t)row * D_);
    const float4* g4 = (const float4*)g;
    const float4* b4 = (const float4*)b;
#pragma unroll
    for (int i = 0; i < 6; i++) {
        float4 gg = g4[lane + i * 32], bb = b4[lane + i * 32];
        float4 o;
        o.x = (v[i].x - mean) * inv * gg.x + bb.x;
        o.y = (v[i].y - mean) * inv * gg.y + bb.y;
        o.z = (v[i].z - mean) * inv * gg.z + bb.z;
        o.w = (v[i].w - mean) * inv * gg.w + bb.w;
        orow[lane + i * 32] = o;
    }
}

// ---------------- tf32 GEMM, 128x64x16 tiles, cp.async double buffered ---------
#define ASTRIDE 20
#define BSTRIDE 72
template<int MODE>
__global__ __launch_bounds__(256)
void gemm_tf32(const float* __restrict__ P0, const float* __restrict__ P1,
               const float* __restrict__ P2) {
    __shared__ __align__(16) unsigned As[2][128 * ASTRIDE];
    __shared__ __align__(16) unsigned Bs[2][16 * BSTRIDE];

    const int tid = threadIdx.x, wid = tid >> 5, lane = tid & 31;
    const int e  = blockIdx.z;
    const int m0 = blockIdx.y * 128;

    int N, K, count, n0;
    const float* Bm;
    float* C;
    const float* Abase;
    if (MODE == 0) {
        K = D_; count = NTOK; Abase = g_xln;
        int bx = blockIdx.x;
        if (bx < 12)      { Bm = P0; C = g_q;    N = D_; n0 = bx * 64; }
        else if (bx < 24) { Bm = P1; C = g_k;    N = D_; n0 = (bx - 12) * 64; }
        else              { Bm = P2; C = g_rlog; N = 96; n0 = (bx - 24) * 64; }
    } else if (MODE == 1) {
        N = DFF_; K = D_; count = g_ecount[e]; n0 = blockIdx.x * 64;
        if (count <= 0 || m0 >= count) return;
        Bm = P0 + (size_t)e * D_ * DFF_;
        C  = g_hbuf + (size_t)e * CAP_ * DFF_;
        Abase = g_xln2;
    } else {
        N = D_; K = DFF_; count = g_ecount[e]; n0 = blockIdx.x * 64;
        if (count <= 0 || m0 >= count) return;
        Bm = P0 + (size_t)e * DFF_ * D_;
        C  = g_sout + (size_t)e * CAP_ * D_;
        Abase = g_hbuf + (size_t)e * CAP_ * DFF_;
    }

    const int sm_r = tid >> 1;
    const int sm_k = (tid & 1) * 8;
    const int brow = tid >> 4;
    const int bcol = (tid & 15) * 4;

    const float* Aptr;
    {
        int r = m0 + sm_r;
        if (r >= count) r = count - 1;
        if (MODE == 1)
            Aptr = Abase + (size_t)g_slot_token[e * CAP_ + r] * D_ + sm_k;
        else
            Aptr = Abase + (size_t)r * K + sm_k;
    }
    int bc_eff = bcol;
    if (n0 + bcol + 4 > N) bc_eff = N - 4 - n0;
    const float* Bptr = Bm + (size_t)brow * N + n0 + bc_eff;

    const int wm0 = (wid & 3) * 32;
    const int wn0 = (wid >> 2) * 32;
    const int gr = lane >> 2, gc = lane & 3;

    float acc[2][4][4];
#pragma unroll
    for (int i = 0; i < 2; i++)
#pragma unroll
        for (int j = 0; j < 4; j++)
#pragma unroll
            for (int q = 0; q < 4; q++) acc[i][j][q] = 0.f;

    const int nk = K / 16;

    cp16(&As[0][sm_r * ASTRIDE + sm_k],     Aptr);
    cp16(&As[0][sm_r * ASTRIDE + sm_k + 4], Aptr + 4);
    cp16(&Bs[0][brow * BSTRIDE + bcol],     Bptr);
    CP_COMMIT();

    for (int kb = 0; kb < nk; kb++) {
        const int buf = kb & 1;
        CP_WAIT0();
        __syncthreads();
        if (kb + 1 < nk) {
            cp16(&As[buf ^ 1][sm_r * ASTRIDE + sm_k],     Aptr + (kb + 1) * 16);
            cp16(&As[buf ^ 1][sm_r * ASTRIDE + sm_k + 4], Aptr + (kb + 1) * 16 + 4);
            cp16(&Bs[buf ^ 1][brow * BSTRIDE + bcol],     Bptr + (size_t)(kb + 1) * 16 * N);
            CP_COMMIT();
        }
        const unsigned* Ab = As[buf];
        const unsigned* Bb = Bs[buf];
#pragma unroll
        for (int kk = 0; kk < 16; kk += 8) {
            unsigned a[2][4];
#pragma unroll
            for (int mf = 0; mf < 2; mf++) {
                int mb = wm0 + mf * 16;
                a[mf][0] = Ab[(mb + gr)     * ASTRIDE + kk + gc];
                a[mf][1] = Ab[(mb + gr + 8) * ASTRIDE + kk + gc];
                a[mf][2] = Ab[(mb + gr)     * ASTRIDE + kk + gc + 4];
                a[mf][3] = Ab[(mb + gr + 8) * ASTRIDE + kk + gc + 4];
            }
#pragma unroll
            for (int nf = 0; nf < 4; nf++) {
                int nb = wn0 + nf * 8 + gr;
                unsigned b[2];
                b[0] = Bb[(kk + gc)     * BSTRIDE + nb];
                b[1] = Bb[(kk + gc + 4) * BSTRIDE + nb];
                mma_tf32(acc[0][nf], a[0], b);
                mma_tf32(acc[1][nf], a[1], b);
            }
        }
    }

#pragma unroll
    for (int mf = 0; mf < 2; mf++) {
        int rbase = m0 + wm0 + mf * 16 + gr;
#pragma unroll
        for (int half = 0; half < 2; half++) {
            int r = rbase + half * 8;
            if (MODE != 0 && r >= count) continue;
            float w = 1.f;
            if (MODE == 2) w = g_slot_w[e * CAP_ + r];
#pragma unroll
            for (int nf = 0; nf < 4; nf++) {
                int cc = n0 + wn0 + nf * 8 + gc * 2;
                if (MODE == 0 && cc + 2 > N) continue;
                float v0 = acc[mf][nf][half * 2 + 0];
                float v1 = acc[mf][nf][half * 2 + 1];
                if (MODE == 1) { v0 = fmaxf(v0, 0.f); v1 = fmaxf(v1, 0.f); }
                else if (MODE == 2) { v0 *= w; v1 *= w; }
                *(float2*)(C + (size_t)r * N + cc) = make_float2(v0, v1);
            }
        }
    }
}

// ---------------- router argmax + per-(h,e) token list build -------------------
__global__ void router_argmax() {
    int idx = blockIdx.x * 256 + threadIdx.x;
    if (idx >= NTOK * H_) return;
    int row = idx / H_, h = idx - row * H_;
    const float* lg = g_rlog + (size_t)row * 96 + h * 8;
    float best = lg[0]; int bi = 0;
#pragma unroll
    for (int e = 1; e < E_; e++) { float v = lg[e]; if (v > best) { best = v; bi = e; } }
    int he = h * E_ + bi;
    int pos = atomicAdd(&g_hcnt[he], 1);
    g_hlist[(size_t)he * NTOK + pos] = row;
}

// ---------------- gathered expert GEMM for vsel/osel ---------------------------
// MODE 0: g_vsel[t] = xln[t,h] @ Wv[h,e]      MODE 1: g_x1[t] = x[t] + attn[t,h] @ Wo[h,e]
// grid: (H_*E_, NTOK/64). Block loads W once, gathers 64 token rows, tf32 MMA.
template<int MODE>
__global__ __launch_bounds__(256)
void sel_gemm(const float* __restrict__ W, const float* __restrict__ xres) {
    __shared__ __align__(16) unsigned Xs[64 * 68];
    __shared__ __align__(16) unsigned Ws[64 * 68];
    __shared__ int ts[64];
    const int he = blockIdx.x;
    const int count = g_hcnt[he];
    const int tile = blockIdx.y;
    if (tile * 64 >= count) return;
    const int h = he >> 3;           // E_ == 8
    const int tid = threadIdx.x, wid = tid >> 5, lane = tid & 31;
    const int gr = lane >> 2, gc = lane & 3;

    if (tid < 64) {
        int idx = tile * 64 + tid;
        if (idx >= count) idx = count - 1;
        ts[tid] = g_hlist[(size_t)he * NTOK + idx];
    }
    __syncthreads();

    // stage W [k=64][n=64] raw bits and gathered X [m=64][k=64]
    {
        int r = tid >> 2, cg = (tid & 3) * 16;
        const float* wsrc = W + (size_t)he * DH_ * DH_ + r * DH_ + cg;
        const float* xsrc = (MODE == 0 ? g_xln : g_attn) + (size_t)ts[r] * D_ + h * DH_ + cg;
#pragma unroll
        for (int i = 0; i < 4; i++) {
            float4 wv = *(const float4*)(wsrc + i * 4);
            Ws[r * 68 + cg + i * 4 + 0] = __float_as_uint(wv.x);
            Ws[r * 68 + cg + i * 4 + 1] = __float_as_uint(wv.y);
            Ws[r * 68 + cg + i * 4 + 2] = __float_as_uint(wv.z);
            Ws[r * 68 + cg + i * 4 + 3] = __float_as_uint(wv.w);
            float4 xv = *(const float4*)(xsrc + i * 4);
            Xs[r * 68 + cg + i * 4 + 0] = __float_as_uint(xv.x);
            Xs[r * 68 + cg + i * 4 + 1] = __float_as_uint(xv.y);
            Xs[r * 68 + cg + i * 4 + 2] = __float_as_uint(xv.z);
            Xs[r * 68 + cg + i * 4 + 3] = __float_as_uint(xv.w);
        }
    }
    __syncthreads();

    const int wm0 = (wid & 1) * 32, wn0 = (wid >> 1) * 16;
    float c[2][2][4];
#pragma unroll
    for (int mf = 0; mf < 2; mf++)
#pragma unroll
        for (int nf = 0; nf < 2; nf++)
#pragma unroll
            for (int q = 0; q < 4; q++) c[mf][nf][q] = 0.f;
#pragma unroll
    for (int kk = 0; kk < 64; kk += 8) {
        unsigned a[2][4], bf[2][2];
#pragma unroll
        for (int mf = 0; mf < 2; mf++) {
            int mb = wm0 + mf * 16;
            a[mf][0] = Xs[(mb + gr)     * 68 + kk + gc];
            a[mf][1] = Xs[(mb + gr + 8) * 68 + kk + gc];
            a[mf][2] = Xs[(mb + gr)     * 68 + kk + gc + 4];
            a[mf][3] = Xs[(mb + gr + 8) * 68 + kk + gc + 4];
        }
#pragma unroll
        for (int nf = 0; nf < 2; nf++) {
            int nb = wn0 + nf * 8 + gr;
            bf[nf][0] = Ws[(kk + gc)     * 68 + nb];
            bf[nf][1] = Ws[(kk + gc + 4) * 68 + nb];
        }
#pragma unroll
        for (int mf = 0; mf < 2; mf++)
#pragma unroll
            for (int nf = 0; nf < 2; nf++)
                mma_tf32(c[mf][nf], a[mf], bf[nf]);
    }

#pragma unroll
    for (int mf = 0; mf < 2; mf++) {
        int ra = wm0 + mf * 16 + gr, rb = ra + 8;
        int ta = ts[ra], tb = ts[rb];
#pragma unroll
        for (int nf = 0; nf < 2; nf++) {
            int col = wn0 + nf * 8 + 2 * gc;
            size_t oa = (size_t)ta * D_ + h * DH_ + col;
            size_t ob = (size_t)tb * D_ + h * DH_ + col;
            if (MODE == 0) {
                *(float2*)(g_vsel + oa) = make_float2(c[mf][nf][0], c[mf][nf][1]);
                *(float2*)(g_vsel + ob) = make_float2(c[mf][nf][2], c[mf][nf][3]);
            } else {
                float2 xa = *(const float2*)(xres + oa);
                float2 xb = *(const float2*)(xres + ob);
                *(float2*)(g_x1 + oa) = make_float2(xa.x + c[mf][nf][0], xa.y + c[mf][nf][1]);
                *(float2*)(g_x1 + ob) = make_float2(xb.x + c[mf][nf][2], xb.y + c[mf][nf][3]);
            }
        }
    }
}

// ---------------- attention pass 1 (tf32 MMA): row stats m_s, l_s --------------
__global__ __launch_bounds__(256)
void attn_pass1() {
    extern __shared__ unsigned dsp[];
    unsigned* uQ = dsp;
    unsigned* uK = dsp + 64 * 68;
    float* Ss = (float*)(dsp + 2 * 64 * 68);
    int s0 = blockIdx.x * 64, h = blockIdx.y, b = blockIdx.z;
    int tid = threadIdx.x, wid = tid >> 5, lane = tid & 31;
    int gr = lane >> 2, gc = lane & 3;
    const float* qb = g_q + (size_t)b * S_ * D_ + h * DH_;
    const float* kb = g_k + (size_t)b * S_ * D_ + h * DH_;
    {
        int r = tid >> 2, dg = (tid & 3) * 16;
        const float* src = qb + (size_t)(s0 + r) * D_ + dg;
#pragma unroll
        for (int i = 0; i < 4; i++) {
            float4 v = *(const float4*)(src + i * 4);
            uQ[r * 68 + dg + i * 4 + 0] = __float_as_uint(v.x);
            uQ[r * 68 + dg + i * 4 + 1] = __float_as_uint(v.y);
            uQ[r * 68 + dg + i * 4 + 2] = __float_as_uint(v.z);
            uQ[r * 68 + dg + i * 4 + 3] = __float_as_uint(v.w);
        }
    }
    const int wm0 = (wid & 1) * 32, wn0 = (wid >> 1) * 16;
    const int rr = tid >> 2, qq = tid & 3;
    float run_m = -INFINITY, run_l = 0.f;

    for (int t0 = 0; t0 <= s0; t0 += 64) {
        {
            int r = tid >> 2, dg = (tid & 3) * 16;
            const float* src = kb + (size_t)(t0 + r) * D_ + dg;
#pragma unroll
            for (int i = 0; i < 4; i++) {
                float4 v = *(const float4*)(src + i * 4);
                uK[(dg + i * 4 + 0) * 68 + r] = __float_as_uint(v.x);
                uK[(dg + i * 4 + 1) * 68 + r] = __float_as_uint(v.y);
                uK[(dg + i * 4 + 2) * 68 + r] = __float_as_uint(v.z);
                uK[(dg + i * 4 + 3) * 68 + r] = __float_as_uint(v.w);
            }
        }
        __syncthreads();
        float c[2][2][4];
#pragma unroll
        for (int mf = 0; mf < 2; mf++)
#pragma unroll
            for (int nf = 0; nf < 2; nf++)
#pragma unroll
                for (int q = 0; q < 4; q++) c[mf][nf][q] = 0.f;
#pragma unroll
        for (int kk = 0; kk < 64; kk += 8) {
            unsigned a[2][4], bf[2][2];
#pragma unroll
            for (int mf = 0; mf < 2; mf++) {
                int mb = wm0 + mf * 16;
                a[mf][0] = uQ[(mb + gr)     * 68 + kk + gc];
                a[mf][1] = uQ[(mb + gr + 8) * 68 + kk + gc];
                a[mf][2] = uQ[(mb + gr)     * 68 + kk + gc + 4];
                a[mf][3] = uQ[(mb + gr + 8) * 68 + kk + gc + 4];
            }
#pragma unroll
            for (int nf = 0; nf < 2; nf++) {
                int nb = wn0 + nf * 8 + gr;
                bf[nf][0] = uK[(kk + gc)     * 68 + nb];
                bf[nf][1] = uK[(kk + gc + 4) * 68 + nb];
            }
#pragma unroll
            for (int mf = 0; mf < 2; mf++)
#pragma unroll
                for (int nf = 0; nf < 2; nf++)
                    mma_tf32(c[mf][nf], a[mf], bf[nf]);
        }
#pragma unroll
        for (int mf = 0; mf < 2; mf++)
#pragma unroll
            for (int nf = 0; nf < 2; nf++) {
                int row = wm0 + mf * 16 + gr, col = wn0 + nf * 8 + 2 * gc;
                *(float2*)&Ss[row * 72 + col]       = make_float2(c[mf][nf][0], c[mf][nf][1]);
                *(float2*)&Ss[(row + 8) * 72 + col] = make_float2(c[mf][nf][2], c[mf][nf][3]);
            }
        __syncthreads();
        float v[16];
#pragma unroll
        for (int i = 0; i < 4; i++) {
            float4 t4 = *(const float4*)&Ss[rr * 72 + qq * 16 + i * 4];
            v[i * 4 + 0] = t4.x; v[i * 4 + 1] = t4.y; v[i * 4 + 2] = t4.z; v[i * 4 + 3] = t4.w;
        }
        int gs = s0 + rr;
        float mx = -INFINITY;
#pragma unroll
        for (int cI = 0; cI < 16; cI++) {
            int gt = t0 + qq * 16 + cI;
            if (gt <= gs) mx = fmaxf(mx, v[cI] * 0.125f);
        }
        mx = fmaxf(mx, __shfl_xor_sync(0xffffffffu, mx, 1));
        mx = fmaxf(mx, __shfl_xor_sync(0xffffffffu, mx, 2));
        float mn = fmaxf(run_m, mx);
        float alpha = __expf(run_m - mn);
        float sum = 0.f;
#pragma unroll
        for (int cI = 0; cI < 16; cI++) {
            int gt = t0 + qq * 16 + cI;
            if (gt <= gs) sum += __expf(v[cI] * 0.125f - mn);
        }
        sum += __shfl_xor_sync(0xffffffffu, sum, 1);
        sum += __shfl_xor_sync(0xffffffffu, sum, 2);
        run_l = run_l * alpha + sum;
        run_m = mn;
    }
    if (qq == 0) {
        int o = (b * H_ + h) * S_ + s0 + rr;
        g_m[o] = run_m; g_l[o] = run_l;
    }
}

// ---------------- attention pass 2 (tf32 MMA): out[t] = sum_s P[s,t] v[s] ------
__global__ __launch_bounds__(256)
void attn_pass2() {
    extern __shared__ unsigned dsp2[];
    unsigned* uK = dsp2;
    unsigned* uQ = dsp2 + 4352;
    unsigned* uV = dsp2 + 8704;
    unsigned* uP = dsp2 + 13056;
    float* srm  = (float*)(dsp2 + 17664);
    float* sinv = srm + 64;
    int t0 = blockIdx.x * 64, h = blockIdx.y, b = blockIdx.z;
    int tid = threadIdx.x, wid = tid >> 5, lane = tid & 31;
    int gr = lane >> 2, gc = lane & 3;
    const float* qb = g_q    + (size_t)b * S_ * D_ + h * DH_;
    const float* kb = g_k    + (size_t)b * S_ * D_ + h * DH_;
    const float* vb = g_vsel + (size_t)b * S_ * D_ + h * DH_;
    {
        int r = tid >> 2, dg = (tid & 3) * 16;
        const float* src = kb + (size_t)(t0 + r) * D_ + dg;
#pragma unroll
        for (int i = 0; i < 4; i++) {
            float4 v = *(const float4*)(src + i * 4);
            uK[(dg + i * 4 + 0) * 68 + r] = __float_as_uint(v.x);
            uK[(dg + i * 4 + 1) * 68 + r] = __float_as_uint(v.y);
            uK[(dg + i * 4 + 2) * 68 + r] = __float_as_uint(v.z);
            uK[(dg + i * 4 + 3) * 68 + r] = __float_as_uint(v.w);
        }
    }
    const int wm0 = (wid & 1) * 32, wn0 = (wid >> 1) * 16;
    float O[2][2][4];
#pragma unroll
    for (int mf = 0; mf < 2; mf++)
#pragma unroll
        for (int nf = 0; nf < 2; nf++)
#pragma unroll
            for (int q = 0; q < 4; q++) O[mf][nf][q] = 0.f;

    for (int st0 = t0; st0 < S_; st0 += 64) {
        {
            int r = tid >> 2, dg = (tid & 3) * 16;
            const float* qsrc = qb + (size_t)(st0 + r) * D_ + dg;
            const float* vsrc = vb + (size_t)(st0 + r) * D_ + dg;
#pragma unroll
            for (int i = 0; i < 4; i++) {
                float4 v = *(const float4*)(qsrc + i * 4);
                uQ[r * 68 + dg + i * 4 + 0] = __float_as_uint(v.x);
                uQ[r * 68 + dg + i * 4 + 1] = __float_as_uint(v.y);
                uQ[r * 68 + dg + i * 4 + 2] = __float_as_uint(v.z);
                uQ[r * 68 + dg + i * 4 + 3] = __float_as_uint(v.w);
                float4 w = *(const float4*)(vsrc + i * 4);
                uV[r * 68 + dg + i * 4 + 0] = __float_as_uint(w.x);
                uV[r * 68 + dg + i * 4 + 1] = __float_as_uint(w.y);
                uV[r * 68 + dg + i * 4 + 2] = __float_as_uint(w.z);
                uV[r * 68 + dg + i * 4 + 3] = __float_as_uint(w.w);
            }
        }
        if (tid < 64) {
            int o = (b * H_ + h) * S_ + st0 + tid;
            srm[tid] = g_m[o]; sinv[tid] = 1.f / g_l[o];
        }
        __syncthreads();
        float c[2][2][4];
#pragma unroll
        for (int mf = 0; mf < 2; mf++)
#pragma unroll
            for (int nf = 0; nf < 2; nf++)
#pragma unroll
                for (int q = 0; q < 4; q++) c[mf][nf][q] = 0.f;
#pragma unroll
        for (int kk = 0; kk < 64; kk += 8) {
            unsigned a[2][4], bf[2][2];
#pragma unroll
            for (int mf = 0; mf < 2; mf++) {
                int mb = wm0 + mf * 16;
                a[mf][0] = uQ[(mb + gr)     * 68 + kk + gc];
                a[mf][1] = uQ[(mb + gr + 8) * 68 + kk + gc];
                a[mf][2] = uQ[(mb + gr)     * 68 + kk + gc + 4];
                a[mf][3] = uQ[(mb + gr + 8) * 68 + kk + gc + 4];
            }
#pragma unroll
            for (int nf = 0; nf < 2; nf++) {
                int nb = wn0 + nf * 8 + gr;
                bf[nf][0] = uK[(kk + gc)     * 68 + nb];
                bf[nf][1] = uK[(kk + gc + 4) * 68 + nb];
            }
#pragma unroll
            for (int mf = 0; mf < 2; mf++)
#pragma unroll
                for (int nf = 0; nf < 2; nf++)
                    mma_tf32(c[mf][nf], a[mf], bf[nf]);
        }
#pragma unroll
        for (int mf = 0; mf < 2; mf++) {
            int sl_a = wm0 + mf * 16 + gr;
            int sl_b = sl_a + 8;
            int gs_a = st0 + sl_a, gs_b = st0 + sl_b;
            float ma = srm[sl_a], ia = sinv[sl_a];
            float mb2 = srm[sl_b], ib = sinv[sl_b];
#pragma unroll
            for (int nf = 0; nf < 2; nf++) {
                int tc = wn0 + nf * 8 + 2 * gc;
                int gt0 = t0 + tc, gt1 = gt0 + 1;
                float p;
                p = (gt0 <= gs_a) ? __expf(c[mf][nf][0] * 0.125f - ma) * ia : 0.f;
                uP[tc * 72 + sl_a] = to_tf32(p);
                p = (gt1 <= gs_a) ? __expf(c[mf][nf][1] * 0.125f - ma) * ia : 0.f;
                uP[(tc + 1) * 72 + sl_a] = to_tf32(p);
                p = (gt0 <= gs_b) ? __expf(c[mf][nf][2] * 0.125f - mb2) * ib : 0.f;
                uP[tc * 72 + sl_b] = to_tf32(p);
                p = (gt1 <= gs_b) ? __expf(c[mf][nf][3] * 0.125f - mb2) * ib : 0.f;
                uP[(tc + 1) * 72 + sl_b] = to_tf32(p);
            }
        }
        __syncthreads();
#pragma unroll
        for (int kk = 0; kk < 64; kk += 8) {
            unsigned a[2][4], bf[2][2];
#pragma unroll
            for (int mf = 0; mf < 2; mf++) {
                int mb = wm0 + mf * 16;
                a[mf][0] = uP[(mb + gr)     * 72 + kk + gc];
                a[mf][1] = uP[(mb + gr + 8) * 72 + kk + gc];
                a[mf][2] = uP[(mb + gr)     * 72 + kk + gc + 4];
                a[mf][3] = uP[(mb + gr + 8) * 72 + kk + gc + 4];
            }
#pragma unroll
            for (int nf = 0; nf < 2; nf++) {
                int nb = wn0 + nf * 8 + gr;
                bf[nf][0] = uV[(kk + gc)     * 68 + nb];
                bf[nf][1] = uV[(kk + gc + 4) * 68 + nb];
            }
#pragma unroll
            for (int mf = 0; mf < 2; mf++)
#pragma unroll
                for (int nf = 0; nf < 2; nf++)
                    mma_tf32(O[mf][nf], a[mf], bf[nf]);
        }
        __syncthreads();
    }
#pragma unroll
    for (int mf = 0; mf < 2; mf++) {
        int trow = t0 + wm0 + mf * 16 + gr;
#pragma unroll
        for (int nf = 0; nf < 2; nf++) {
            int fc = wn0 + nf * 8 + 2 * gc;
            *(float2*)(g_attn + (size_t)(b * S_ + trow) * D_ + h * DH_ + fc)
                = make_float2(O[mf][nf][0], O[mf][nf][1]);
            *(float2*)(g_attn + (size_t)(b * S_ + trow + 8) * D_ + h * DH_ + fc)
                = make_float2(O[mf][nf][2], O[mf][nf][3]);
        }
    }
}

// ---------------- FFN gate + top-2 (warp per token) ----------------------------
__global__ void gate_kernel(const float* __restrict__ gff) {
    int wid = threadIdx.x >> 5, lane = threadIdx.x & 31;
    int row = blockIdx.x * 8 + wid;
    const float* xr = g_xln2 + (size_t)row * D_;
    float acc[8] = {};
    for (int d = lane; d < D_; d += 32) {
        float xv = xr[d];
        float4 gA = *(const float4*)(gff + (size_t)d * E_);
        float4 gB = *(const float4*)(gff + (size_t)d * E_ + 4);
        acc[0] += xv * gA.x; acc[1] += xv * gA.y; acc[2] += xv * gA.z; acc[3] += xv * gA.w;
        acc[4] += xv * gB.x; acc[5] += xv * gB.y; acc[6] += xv * gB.z; acc[7] += xv * gB.w;
    }
#pragma unroll
    for (int off = 16; off > 0; off >>= 1)
#pragma unroll
        for (int i = 0; i < 8; i++)
            acc[i] += __shfl_down_sync(0xffffffffu, acc[i], off);
    if (lane == 0) {
        int i0 = 0; float v0 = acc[0];
#pragma unroll
        for (int e = 1; e < E_; e++) if (acc[e] > v0) { v0 = acc[e]; i0 = e; }
        int i1 = -1; float v1 = -3.4e38f;
#pragma unroll
        for (int e = 0; e < E_; e++) { if (e == i0) continue; if (acc[e] > v1) { v1 = acc[e]; i1 = e; } }
        float e1 = expf(v1 - v0);
        float z = 1.f + e1;
        g_tk_idx[row * 2] = i0; g_tk_idx[row * 2 + 1] = i1;
        g_tk_prob[row * 2] = 1.f / z; g_tk_prob[row * 2 + 1] = e1 / z;
    }
}

// ---------------- capacity + deterministic slot assignment --------------------
__global__ void capacity_kernel() {
    int tid = threadIdx.x; // 256 = 8 warps, warp per expert
    int w = tid >> 5, lane = tid & 31;
    if (w < E_) {
        int e = w, c = 0;
        for (int i0 = 0; i0 < NTOK * 2; i0 += 32) {
            int i = i0 + lane;
            int idx = g_tk_idx[i];
            bool match = (idx == e);
            unsigned msk = __ballot_sync(0xffffffffu, match);
            if (match) {
                int rank = c + __popc(msk & ((1u << lane) - 1u));
                if (rank < CAP_) {
                    g_slot_token[e * CAP_ + rank] = i >> 1;
                    g_token_slot[i] = e * CAP_ + rank;
                } else {
                    g_token_slot[i] = -1;
                }
            }
            c += __popc(msk);
        }
        if (lane == 0) g_ecount[e] = (c < CAP_) ? c : CAP_;
    }
    __syncthreads();
    for (int t = tid; t < NTOK; t += 256) {
        int s0 = g_token_slot[2 * t], s1 = g_token_slot[2 * t + 1];
        float p0 = (s0 >= 0) ? g_tk_prob[2 * t]     : 0.f;
        float p1 = (s1 >= 0) ? g_tk_prob[2 * t + 1] : 0.f;
        float inv = 1.f / (p0 + p1 + 1e-9f);
        if (s0 >= 0) g_slot_w[s0] = p0 * inv;
        if (s1 >= 0) g_slot_w[s1] = p1 * inv;
    }
}

// ---------------- combine: out = x1 + f (warp per row, float4) -----------------
__global__ void combine_kernel(float* __restrict__ out) {
    int wid = threadIdx.x >> 5, lane = threadIdx.x & 31;
    int row = blockIdx.x * 8 + wid;
    int s0 = g_token_slot[2 * row], s1 = g_token_slot[2 * row + 1];
    const float4* xr = (const float4*)(g_x1 + (size_t)row * D_);
    const float4* f0 = (s0 >= 0) ? (const float4*)(g_sout + (size_t)s0 * D_) : nullptr;
    const float4* f1 = (s1 >= 0) ? (const float4*)(g_sout + (size_t)s1 * D_) : nullptr;
    float4* orow = (float4*)(out + (size_t)row * D_);
#pragma unroll
    for (int i = 0; i < 6; i++) {
        int c = lane + i * 32;
        float4 v = xr[c];
        if (f0) { float4 a = f0[c]; v.x += a.x; v.y += a.y; v.z += a.z; v.w += a.w; }
        if (f1) { float4 a = f1[c]; v.x += a.x; v.y += a.y; v.z += a.z; v.w += a.w; }
        orow[c] = v;
    }
}

// ---------------- aux losses (parallelized) ------------------------------------
__global__ void aux_kernel(float* __restrict__ out, int out_size) {
    __shared__ float ic_sh[E_];
    __shared__ float sa;
    int tid = threadIdx.x, w = tid >> 5, lane = tid & 31;
    if (w < E_) {
        int c = g_ecount[w];
        float s = 0.f;
        for (int r = lane; r < c; r += 32) s += g_slot_w[w * CAP_ + r];
#pragma unroll
        for (int o = 16; o > 0; o >>= 1) s += __shfl_down_sync(0xffffffffu, s, o);
        if (lane == 0) ic_sh[w] = s;
    }
    __syncthreads();
    if (tid == 0) {
        const float scale = 0.01f / 2048.f;
        float es = 0.f;
        for (int i = 0; i < H_ * E_; i++) es += g_hcnt[i] * scale;
        float a1 = 0.f;
        for (int i = 0; i < H_ * E_; i++) {
            float p = (g_hcnt[i] * scale) / (es + 1e-9f);
            a1 += p * p;
        }
        a1 *= (float)(E_ * H_);
        float tcs = 0.f, ics = 0.f;
        for (int e = 0; e < E_; e++) { tcs += (float)g_ecount[e]; ics += ic_sh[e]; }
        float a2 = 0.f;
        for (int e = 0; e < E_; e++) a2 += ((float)g_ecount[e] / tcs) * (ic_sh[e] / ics);
        a2 *= (float)E_;
        sa = a1 + a2;
    }
    __syncthreads();
    for (int i = NOUT + tid; i < out_size; i += blockDim.x) out[i] = sa;
}

// ---------------- launch -------------------------------------------------------
extern "C" void kernel_launch(void* const* d_in, const int* in_sizes, int n_in,
                              void* d_out, int out_size) {
    const float* x   = (const float*)d_in[0];
    // d_in[1] = mask (pure causal 0/-1e9, applied analytically)
    const float* Wq  = (const float*)d_in[2];
    const float* Wk  = (const float*)d_in[3];
    const float* Wv  = (const float*)d_in[4];
    const float* Wo  = (const float*)d_in[5];
    const float* Wr  = (const float*)d_in[6];
    const float* g1  = (const float*)d_in[7];
    const float* b1  = (const float*)d_in[8];
    const float* g2  = (const float*)d_in[9];
    const float* b2  = (const float*)d_in[10];
    const float* gff = (const float*)d_in[11];
    const float* W1  = (const float*)d_in[12];
    const float* W2  = (const float*)d_in[13];
    float* out = (float*)d_out;

    float *p_xln, *p_x1, *p_xln2;
    cudaGetSymbolAddress((void**)&p_xln,  g_xln);
    cudaGetSymbolAddress((void**)&p_x1,   g_x1);
    cudaGetSymbolAddress((void**)&p_xln2, g_xln2);

    const int pass1_smem = (2 * 64 * 68 + 64 * 72) * 4;
    const int pass2_smem = (3 * 64 * 68 + 64 * 72 + 128) * 4;
    cudaFuncSetAttribute(attn_pass1, cudaFuncAttributeMaxDynamicSharedMemorySize, pass1_smem);
    cudaFuncSetAttribute(attn_pass2, cudaFuncAttributeMaxDynamicSharedMemorySize, pass2_smem);

    ln_kernel<<<NTOK / 8, 256>>>(x, g1, b1, p_xln, 1);
    gemm_tf32<0><<<dim3(26, NTOK / 128, 1), 256>>>(Wq, Wk, Wr);   // Q, K, router fused
    router_argmax<<<(NTOK * H_ + 255) / 256, 256>>>();
    sel_gemm<0><<<dim3(H_ * E_, NTOK / 64), 256>>>(Wv, nullptr);
    attn_pass1<<<dim3(S_ / 64, H_, B_), 256, pass1_smem>>>();
    attn_pass2<<<dim3(S_ / 64, H_, B_), 256, pass2_smem>>>();
    sel_gemm<1><<<dim3(H_ * E_, NTOK / 64), 256>>>(Wo, x);
    ln_kernel<<<NTOK / 8, 256>>>(p_x1, g2, b2, p_xln2, 0);
    gate_kernel<<<NTOK / 8, 256>>>(gff);
    capacity_kernel<<<1, 256>>>();
    gemm_tf32<1><<<dim3(DFF_ / 64, (CAP_ + 127) / 128, E_), 256>>>(W1, nullptr, nullptr);
    gemm_tf32<2><<<dim3(D_ / 64, (CAP_ + 127) / 128, E_), 256>>>(W2, nullptr, nullptr);
    combine_kernel<<<NTOK / 8, 256>>>(out);
    if (out_size > NOUT) aux_kernel<<<1, 256>>>(out, out_size);
}

// round 14
// speedup vs baseline: 1.6233x; 1.0214x over previous
#include <cuda_runtime.h>
#include <math.h>

#define B_ 2
#define S_ 1024
#define D_ 768
#define H_ 12
#define E_ 8
#define DH_ 64
#define DFF_ 2048
#define NTOK (B_*S_)
#define CAP_ 320
#define NOUT (NTOK*D_)

// ---------------- scratch (device globals; no allocation allowed) -------------
__device__ float g_xln [NTOK*D_];
__device__ float g_q   [NTOK*D_];
__device__ float g_k   [NTOK*D_];
__device__ float g_vsel[NTOK*D_];
__device__ float g_attn[NTOK*D_];
__device__ float g_x1  [NTOK*D_];
__device__ float g_xln2[NTOK*D_];
__device__ float g_rlog[NTOK*(H_*E_)];
__device__ int   g_hcnt[H_*E_];
__device__ int   g_hlist[H_*E_*NTOK];
__device__ float g_m[B_*H_*S_];
__device__ float g_l[B_*H_*S_];
__device__ int   g_tk_idx[NTOK*2];
__device__ float g_tk_prob[NTOK*2];
__device__ int   g_token_slot[NTOK*2];
__device__ int   g_slot_token[E_*CAP_];
__device__ float g_slot_w[E_*CAP_];
__device__ int   g_ecount[E_];
__device__ float g_hbuf[E_*CAP_*DFF_];
__device__ float g_sout[E_*CAP_*D_];

// ---------------- tf32 tensor-core helpers -------------------------------------
__device__ __forceinline__ unsigned to_tf32(float f) {
    unsigned u; asm("cvt.rna.tf32.f32 %0,%1;" : "=r"(u) : "f"(f)); return u;
}
__device__ __forceinline__ void mma_tf32(float c[4], const unsigned a[4], const unsigned b[2]) {
    asm("mma.sync.aligned.m16n8k8.row.col.f32.tf32.tf32.f32 "
        "{%0,%1,%2,%3},{%4,%5,%6,%7},{%8,%9},{%0,%1,%2,%3};"
        : "+f"(c[0]), "+f"(c[1]), "+f"(c[2]), "+f"(c[3])
        : "r"(a[0]), "r"(a[1]), "r"(a[2]), "r"(a[3]), "r"(b[0]), "r"(b[1]));
}
__device__ __forceinline__ void cp16(void* smem, const void* g) {
    unsigned saddr = (unsigned)__cvta_generic_to_shared(smem);
    asm volatile("cp.async.cg.shared.global [%0], [%1], 16;" :: "r"(saddr), "l"(g));
}
#define CP_COMMIT() asm volatile("cp.async.commit_group;" ::: "memory")
#define CP_WAIT0()  asm volatile("cp.async.wait_group 0;" ::: "memory")

// ---------------- LayerNorm (warp per row, float4); optional counter clear -----
__global__ void ln_kernel(const float* __restrict__ x, const float* __restrict__ g,
                          const float* __restrict__ b, float* __restrict__ out,
                          int clear_hard) {
    if (clear_hard && blockIdx.x == 0 && threadIdx.x < H_ * E_) g_hcnt[threadIdx.x] = 0;
    int wid = threadIdx.x >> 5, lane = threadIdx.x & 31;
    int row = blockIdx.x * 8 + wid;
    const float4* xr = (const float4*)(x + (size_t)row * D_);
    float4 v[6];
    float s = 0.f, s2 = 0.f;
#pragma unroll
    for (int i = 0; i < 6; i++) {
        v[i] = xr[lane + i * 32];
        s  += v[i].x + v[i].y + v[i].z + v[i].w;
        s2 += v[i].x * v[i].x + v[i].y * v[i].y + v[i].z * v[i].z + v[i].w * v[i].w;
    }
#pragma unroll
    for (int o = 16; o > 0; o >>= 1) {
        s  += __shfl_xor_sync(0xffffffffu, s,  o);
        s2 += __shfl_xor_sync(0xffffffffu, s2, o);
    }
    float mean = s * (1.f / D_);
    float inv  = rsqrtf(s2 * (1.f / D_) - mean * mean + 1e-5f);
    float4* orow = (float4*)(out + (size_t)row * D_);
    const float4* g4 = (const float4*)g;
    const float4* b4 = (const float4*)b;
#pragma unroll
    for (int i = 0; i < 6; i++) {
        float4 gg = g4[lane + i * 32], bb = b4[lane + i * 32];
        float4 o;
        o.x = (v[i].x - mean) * inv * gg.x + bb.x;
        o.y = (v[i].y - mean) * inv * gg.y + bb.y;
        o.z = (v[i].z - mean) * inv * gg.z + bb.z;
        o.w = (v[i].w - mean) * inv * gg.w + bb.w;
        orow[lane + i * 32] = o;
    }
}

// ---------------- LN2 + FFN gate fused (warp per row, gff staged in smem) ------
__global__ void ln_gate_kernel(const float* __restrict__ x, const float* __restrict__ g,
                               const float* __restrict__ b, const float* __restrict__ gff,
                               float* __restrict__ out) {
    __shared__ float sgff[D_ * E_];   // 24 KB
    int tid = threadIdx.x;
    // coalesced stage of the whole gate matrix
    for (int i = tid; i < (D_ * E_) / 4; i += 256)
        *(float4*)&sgff[i * 4] = *(const float4*)(gff + i * 4);

    int wid = tid >> 5, lane = tid & 31;
    int row = blockIdx.x * 8 + wid;
    const float4* xr = (const float4*)(x + (size_t)row * D_);
    float4 v[6];
    float s = 0.f, s2 = 0.f;
#pragma unroll
    for (int i = 0; i < 6; i++) {
        v[i] = xr[lane + i * 32];
        s  += v[i].x + v[i].y + v[i].z + v[i].w;
        s2 += v[i].x * v[i].x + v[i].y * v[i].y + v[i].z * v[i].z + v[i].w * v[i].w;
    }
#pragma unroll
    for (int o = 16; o > 0; o >>= 1) {
        s  += __shfl_xor_sync(0xffffffffu, s,  o);
        s2 += __shfl_xor_sync(0xffffffffu, s2, o);
    }
    float mean = s * (1.f / D_);
    float inv  = rsqrtf(s2 * (1.f / D_) - mean * mean + 1e-5f);
    float4* orow = (float4*)(out + (size_t)row * D_);
    const float4* g4 = (const float4*)g;
    const float4* b4 = (const float4*)b;
    __syncthreads();   // gff staged
    float acc[8] = {};
#pragma unroll
    for (int i = 0; i < 6; i++) {
        int c = lane + i * 32;
        float4 gg = g4[c], bb = b4[c];
        float4 o;
        o.x = (v[i].x - mean) * inv * gg.x + bb.x;
        o.y = (v[i].y - mean) * inv * gg.y + bb.y;
        o.z = (v[i].z - mean) * inv * gg.z + bb.z;
        o.w = (v[i].w - mean) * inv * gg.w + bb.w;
        orow[c] = o;
        float ov[4] = { o.x, o.y, o.z, o.w };
#pragma unroll
        for (int j = 0; j < 4; j++) {
            float xv = ov[j];
            const float* gr = &sgff[(c * 4 + j) * E_];
            float4 gA = *(const float4*)gr;
            float4 gB = *(const float4*)(gr + 4);
            acc[0] += xv * gA.x; acc[1] += xv * gA.y; acc[2] += xv * gA.z; acc[3] += xv * gA.w;
            acc[4] += xv * gB.x; acc[5] += xv * gB.y; acc[6] += xv * gB.z; acc[7] += xv * gB.w;
        }
    }
#pragma unroll
    for (int off = 16; off > 0; off >>= 1)
#pragma unroll
        for (int i = 0; i < 8; i++)
            acc[i] += __shfl_down_sync(0xffffffffu, acc[i], off);
    if (lane == 0) {
        int i0 = 0; float v0 = acc[0];
#pragma unroll
        for (int e = 1; e < E_; e++) if (acc[e] > v0) { v0 = acc[e]; i0 = e; }
        int i1 = -1; float v1 = -3.4e38f;
#pragma unroll
        for (int e = 0; e < E_; e++) { if (e == i0) continue; if (acc[e] > v1) { v1 = acc[e]; i1 = e; } }
        float e1 = expf(v1 - v0);
        float z = 1.f + e1;
        g_tk_idx[row * 2] = i0; g_tk_idx[row * 2 + 1] = i1;
        g_tk_prob[row * 2] = 1.f / z; g_tk_prob[row * 2 + 1] = e1 / z;
    }
}

// ---------------- tf32 GEMM, 128x64x16 tiles, cp.async double buffered ---------
#define ASTRIDE 20
#define BSTRIDE 72
template<int MODE>
__global__ __launch_bounds__(256)
void gemm_tf32(const float* __restrict__ P0, const float* __restrict__ P1,
               const float* __restrict__ P2) {
    __shared__ __align__(16) unsigned As[2][128 * ASTRIDE];
    __shared__ __align__(16) unsigned Bs[2][16 * BSTRIDE];

    const int tid = threadIdx.x, wid = tid >> 5, lane = tid & 31;
    const int e  = blockIdx.z;
    const int m0 = blockIdx.y * 128;

    int N, K, count, n0;
    const float* Bm;
    float* C;
    const float* Abase;
    if (MODE == 0) {
        K = D_; count = NTOK; Abase = g_xln;
        int bx = blockIdx.x;
        if (bx < 12)      { Bm = P0; C = g_q;    N = D_; n0 = bx * 64; }
        else if (bx < 24) { Bm = P1; C = g_k;    N = D_; n0 = (bx - 12) * 64; }
        else              { Bm = P2; C = g_rlog; N = 96; n0 = (bx - 24) * 64; }
    } else if (MODE == 1) {
        N = DFF_; K = D_; count = g_ecount[e]; n0 = blockIdx.x * 64;
        if (count <= 0 || m0 >= count) return;
        Bm = P0 + (size_t)e * D_ * DFF_;
        C  = g_hbuf + (size_t)e * CAP_ * DFF_;
        Abase = g_xln2;
    } else {
        N = D_; K = DFF_; count = g_ecount[e]; n0 = blockIdx.x * 64;
        if (count <= 0 || m0 >= count) return;
        Bm = P0 + (size_t)e * DFF_ * D_;
        C  = g_sout + (size_t)e * CAP_ * D_;
        Abase = g_hbuf + (size_t)e * CAP_ * DFF_;
    }

    const int sm_r = tid >> 1;
    const int sm_k = (tid & 1) * 8;
    const int brow = tid >> 4;
    const int bcol = (tid & 15) * 4;

    const float* Aptr;
    {
        int r = m0 + sm_r;
        if (r >= count) r = count - 1;
        if (MODE == 1)
            Aptr = Abase + (size_t)g_slot_token[e * CAP_ + r] * D_ + sm_k;
        else
            Aptr = Abase + (size_t)r * K + sm_k;
    }
    int bc_eff = bcol;
    if (n0 + bcol + 4 > N) bc_eff = N - 4 - n0;
    const float* Bptr = Bm + (size_t)brow * N + n0 + bc_eff;

    const int wm0 = (wid & 3) * 32;
    const int wn0 = (wid >> 2) * 32;
    const int gr = lane >> 2, gc = lane & 3;

    float acc[2][4][4];
#pragma unroll
    for (int i = 0; i < 2; i++)
#pragma unroll
        for (int j = 0; j < 4; j++)
#pragma unroll
            for (int q = 0; q < 4; q++) acc[i][j][q] = 0.f;

    const int nk = K / 16;

    cp16(&As[0][sm_r * ASTRIDE + sm_k],     Aptr);
    cp16(&As[0][sm_r * ASTRIDE + sm_k + 4], Aptr + 4);
    cp16(&Bs[0][brow * BSTRIDE + bcol],     Bptr);
    CP_COMMIT();

    for (int kb = 0; kb < nk; kb++) {
        const int buf = kb & 1;
        CP_WAIT0();
        __syncthreads();
        if (kb + 1 < nk) {
            cp16(&As[buf ^ 1][sm_r * ASTRIDE + sm_k],     Aptr + (kb + 1) * 16);
            cp16(&As[buf ^ 1][sm_r * ASTRIDE + sm_k + 4], Aptr + (kb + 1) * 16 + 4);
            cp16(&Bs[buf ^ 1][brow * BSTRIDE + bcol],     Bptr + (size_t)(kb + 1) * 16 * N);
            CP_COMMIT();
        }
        const unsigned* Ab = As[buf];
        const unsigned* Bb = Bs[buf];
#pragma unroll
        for (int kk = 0; kk < 16; kk += 8) {
            unsigned a[2][4];
#pragma unroll
            for (int mf = 0; mf < 2; mf++) {
                int mb = wm0 + mf * 16;
                a[mf][0] = Ab[(mb + gr)     * ASTRIDE + kk + gc];
                a[mf][1] = Ab[(mb + gr + 8) * ASTRIDE + kk + gc];
                a[mf][2] = Ab[(mb + gr)     * ASTRIDE + kk + gc + 4];
                a[mf][3] = Ab[(mb + gr + 8) * ASTRIDE + kk + gc + 4];
            }
#pragma unroll
            for (int nf = 0; nf < 4; nf++) {
                int nb = wn0 + nf * 8 + gr;
                unsigned b[2];
                b[0] = Bb[(kk + gc)     * BSTRIDE + nb];
                b[1] = Bb[(kk + gc + 4) * BSTRIDE + nb];
                mma_tf32(acc[0][nf], a[0], b);
                mma_tf32(acc[1][nf], a[1], b);
            }
        }
    }

#pragma unroll
    for (int mf = 0; mf < 2; mf++) {
        int rbase = m0 + wm0 + mf * 16 + gr;
#pragma unroll
        for (int half = 0; half < 2; half++) {
            int r = rbase + half * 8;
            if (MODE != 0 && r >= count) continue;
            float w = 1.f;
            if (MODE == 2) w = g_slot_w[e * CAP_ + r];
#pragma unroll
            for (int nf = 0; nf < 4; nf++) {
                int cc = n0 + wn0 + nf * 8 + gc * 2;
                if (MODE == 0 && cc + 2 > N) continue;
                float v0 = acc[mf][nf][half * 2 + 0];
                float v1 = acc[mf][nf][half * 2 + 1];
                if (MODE == 1) { v0 = fmaxf(v0, 0.f); v1 = fmaxf(v1, 0.f); }
                else if (MODE == 2) { v0 *= w; v1 *= w; }
                *(float2*)(C + (size_t)r * N + cc) = make_float2(v0, v1);
            }
        }
    }
}

// ---------------- router argmax + per-(h,e) token list build -------------------
__global__ void router_argmax() {
    int idx = blockIdx.x * 256 + threadIdx.x;
    if (idx >= NTOK * H_) return;
    int row = idx / H_, h = idx - row * H_;
    const float* lg = g_rlog + (size_t)row * 96 + h * 8;
    float best = lg[0]; int bi = 0;
#pragma unroll
    for (int e = 1; e < E_; e++) { float v = lg[e]; if (v > best) { best = v; bi = e; } }
    int he = h * E_ + bi;
    int pos = atomicAdd(&g_hcnt[he], 1);
    g_hlist[(size_t)he * NTOK + pos] = row;
}

// ---------------- gathered expert GEMM for vsel/osel ---------------------------
template<int MODE>
__global__ __launch_bounds__(256)
void sel_gemm(const float* __restrict__ W, const float* __restrict__ xres) {
    __shared__ __align__(16) unsigned Xs[64 * 68];
    __shared__ __align__(16) unsigned Ws[64 * 68];
    __shared__ int ts[64];
    const int he = blockIdx.x;
    const int count = g_hcnt[he];
    const int tile = blockIdx.y;
    if (tile * 64 >= count) return;
    const int h = he >> 3;
    const int tid = threadIdx.x, wid = tid >> 5, lane = tid & 31;
    const int gr = lane >> 2, gc = lane & 3;

    if (tid < 64) {
        int idx = tile * 64 + tid;
        if (idx >= count) idx = count - 1;
        ts[tid] = g_hlist[(size_t)he * NTOK + idx];
    }
    __syncthreads();

    {
        int r = tid >> 2, cg = (tid & 3) * 16;
        const float* wsrc = W + (size_t)he * DH_ * DH_ + r * DH_ + cg;
        const float* xsrc = (MODE == 0 ? g_xln : g_attn) + (size_t)ts[r] * D_ + h * DH_ + cg;
#pragma unroll
        for (int i = 0; i < 4; i++) {
            float4 wv = *(const float4*)(wsrc + i * 4);
            Ws[r * 68 + cg + i * 4 + 0] = __float_as_uint(wv.x);
            Ws[r * 68 + cg + i * 4 + 1] = __float_as_uint(wv.y);
            Ws[r * 68 + cg + i * 4 + 2] = __float_as_uint(wv.z);
            Ws[r * 68 + cg + i * 4 + 3] = __float_as_uint(wv.w);
            float4 xv = *(const float4*)(xsrc + i * 4);
            Xs[r * 68 + cg + i * 4 + 0] = __float_as_uint(xv.x);
            Xs[r * 68 + cg + i * 4 + 1] = __float_as_uint(xv.y);
            Xs[r * 68 + cg + i * 4 + 2] = __float_as_uint(xv.z);
            Xs[r * 68 + cg + i * 4 + 3] = __float_as_uint(xv.w);
        }
    }
    __syncthreads();

    const int wm0 = (wid & 1) * 32, wn0 = (wid >> 1) * 16;
    float c[2][2][4];
#pragma unroll
    for (int mf = 0; mf < 2; mf++)
#pragma unroll
        for (int nf = 0; nf < 2; nf++)
#pragma unroll
            for (int q = 0; q < 4; q++) c[mf][nf][q] = 0.f;
#pragma unroll
    for (int kk = 0; kk < 64; kk += 8) {
        unsigned a[2][4], bf[2][2];
#pragma unroll
        for (int mf = 0; mf < 2; mf++) {
            int mb = wm0 + mf * 16;
            a[mf][0] = Xs[(mb + gr)     * 68 + kk + gc];
            a[mf][1] = Xs[(mb + gr + 8) * 68 + kk + gc];
            a[mf][2] = Xs[(mb + gr)     * 68 + kk + gc + 4];
            a[mf][3] = Xs[(mb + gr + 8) * 68 + kk + gc + 4];
        }
#pragma unroll
        for (int nf = 0; nf < 2; nf++) {
            int nb = wn0 + nf * 8 + gr;
            bf[nf][0] = Ws[(kk + gc)     * 68 + nb];
            bf[nf][1] = Ws[(kk + gc + 4) * 68 + nb];
        }
#pragma unroll
        for (int mf = 0; mf < 2; mf++)
#pragma unroll
            for (int nf = 0; nf < 2; nf++)
                mma_tf32(c[mf][nf], a[mf], bf[nf]);
    }

#pragma unroll
    for (int mf = 0; mf < 2; mf++) {
        int ra = wm0 + mf * 16 + gr, rb = ra + 8;
        int ta = ts[ra], tb = ts[rb];
#pragma unroll
        for (int nf = 0; nf < 2; nf++) {
            int col = wn0 + nf * 8 + 2 * gc;
            size_t oa = (size_t)ta * D_ + h * DH_ + col;
            size_t ob = (size_t)tb * D_ + h * DH_ + col;
            if (MODE == 0) {
                *(float2*)(g_vsel + oa) = make_float2(c[mf][nf][0], c[mf][nf][1]);
                *(float2*)(g_vsel + ob) = make_float2(c[mf][nf][2], c[mf][nf][3]);
            } else {
                float2 xa = *(const float2*)(xres + oa);
                float2 xb = *(const float2*)(xres + ob);
                *(float2*)(g_x1 + oa) = make_float2(xa.x + c[mf][nf][0], xa.y + c[mf][nf][1]);
                *(float2*)(g_x1 + ob) = make_float2(xb.x + c[mf][nf][2], xb.y + c[mf][nf][3]);
            }
        }
    }
}

// ---------------- attention pass 1 (tf32 MMA): row stats m_s, l_s --------------
__global__ __launch_bounds__(256)
void attn_pass1() {
    extern __shared__ unsigned dsp[];
    unsigned* uQ = dsp;
    unsigned* uK = dsp + 64 * 68;
    float* Ss = (float*)(dsp + 2 * 64 * 68);
    int s0 = blockIdx.x * 64, h = blockIdx.y, b = blockIdx.z;
    int tid = threadIdx.x, wid = tid >> 5, lane = tid & 31;
    int gr = lane >> 2, gc = lane & 3;
    const float* qb = g_q + (size_t)b * S_ * D_ + h * DH_;
    const float* kb = g_k + (size_t)b * S_ * D_ + h * DH_;
    {
        int r = tid >> 2, dg = (tid & 3) * 16;
        const float* src = qb + (size_t)(s0 + r) * D_ + dg;
#pragma unroll
        for (int i = 0; i < 4; i++) {
            float4 v = *(const float4*)(src + i * 4);
            uQ[r * 68 + dg + i * 4 + 0] = __float_as_uint(v.x);
            uQ[r * 68 + dg + i * 4 + 1] = __float_as_uint(v.y);
            uQ[r * 68 + dg + i * 4 + 2] = __float_as_uint(v.z);
            uQ[r * 68 + dg + i * 4 + 3] = __float_as_uint(v.w);
        }
    }
    const int wm0 = (wid & 1) * 32, wn0 = (wid >> 1) * 16;
    const int rr = tid >> 2, qq = tid & 3;
    float run_m = -INFINITY, run_l = 0.f;

    for (int t0 = 0; t0 <= s0; t0 += 64) {
        {
            int r = tid >> 2, dg = (tid & 3) * 16;
            const float* src = kb + (size_t)(t0 + r) * D_ + dg;
#pragma unroll
            for (int i = 0; i < 4; i++) {
                float4 v = *(const float4*)(src + i * 4);
                uK[(dg + i * 4 + 0) * 68 + r] = __float_as_uint(v.x);
                uK[(dg + i * 4 + 1) * 68 + r] = __float_as_uint(v.y);
                uK[(dg + i * 4 + 2) * 68 + r] = __float_as_uint(v.z);
                uK[(dg + i * 4 + 3) * 68 + r] = __float_as_uint(v.w);
            }
        }
        __syncthreads();
        float c[2][2][4];
#pragma unroll
        for (int mf = 0; mf < 2; mf++)
#pragma unroll
            for (int nf = 0; nf < 2; nf++)
#pragma unroll
                for (int q = 0; q < 4; q++) c[mf][nf][q] = 0.f;
#pragma unroll
        for (int kk = 0; kk < 64; kk += 8) {
            unsigned a[2][4], bf[2][2];
#pragma unroll
            for (int mf = 0; mf < 2; mf++) {
                int mb = wm0 + mf * 16;
                a[mf][0] = uQ[(mb + gr)     * 68 + kk + gc];
                a[mf][1] = uQ[(mb + gr + 8) * 68 + kk + gc];
                a[mf][2] = uQ[(mb + gr)     * 68 + kk + gc + 4];
                a[mf][3] = uQ[(mb + gr + 8) * 68 + kk + gc + 4];
            }
#pragma unroll
            for (int nf = 0; nf < 2; nf++) {
                int nb = wn0 + nf * 8 + gr;
                bf[nf][0] = uK[(kk + gc)     * 68 + nb];
                bf[nf][1] = uK[(kk + gc + 4) * 68 + nb];
            }
#pragma unroll
            for (int mf = 0; mf < 2; mf++)
#pragma unroll
                for (int nf = 0; nf < 2; nf++)
                    mma_tf32(c[mf][nf], a[mf], bf[nf]);
        }
#pragma unroll
        for (int mf = 0; mf < 2; mf++)
#pragma unroll
            for (int nf = 0; nf < 2; nf++) {
                int row = wm0 + mf * 16 + gr, col = wn0 + nf * 8 + 2 * gc;
                *(float2*)&Ss[row * 72 + col]       = make_float2(c[mf][nf][0], c[mf][nf][1]);
                *(float2*)&Ss[(row + 8) * 72 + col] = make_float2(c[mf][nf][2], c[mf][nf][3]);
            }
        __syncthreads();
        float v[16];
#pragma unroll
        for (int i = 0; i < 4; i++) {
            float4 t4 = *(const float4*)&Ss[rr * 72 + qq * 16 + i * 4];
            v[i * 4 + 0] = t4.x; v[i * 4 + 1] = t4.y; v[i * 4 + 2] = t4.z; v[i * 4 + 3] = t4.w;
        }
        int gs = s0 + rr;
        float mx = -INFINITY;
#pragma unroll
        for (int cI = 0; cI < 16; cI++) {
            int gt = t0 + qq * 16 + cI;
            if (gt <= gs) mx = fmaxf(mx, v[cI] * 0.125f);
        }
        mx = fmaxf(mx, __shfl_xor_sync(0xffffffffu, mx, 1));
        mx = fmaxf(mx, __shfl_xor_sync(0xffffffffu, mx, 2));
        float mn = fmaxf(run_m, mx);
        float alpha = __expf(run_m - mn);
        float sum = 0.f;
#pragma unroll
        for (int cI = 0; cI < 16; cI++) {
            int gt = t0 + qq * 16 + cI;
            if (gt <= gs) sum += __expf(v[cI] * 0.125f - mn);
        }
        sum += __shfl_xor_sync(0xffffffffu, sum, 1);
        sum += __shfl_xor_sync(0xffffffffu, sum, 2);
        run_l = run_l * alpha + sum;
        run_m = mn;
    }
    if (qq == 0) {
        int o = (b * H_ + h) * S_ + s0 + rr;
        g_m[o] = run_m; g_l[o] = run_l;
    }
}

// ---------------- attention pass 2 (tf32 MMA): out[t] = sum_s P[s,t] v[s] ------
__global__ __launch_bounds__(256)
void attn_pass2() {
    extern __shared__ unsigned dsp2[];
    unsigned* uK = dsp2;
    unsigned* uQ = dsp2 + 4352;
    unsigned* uV = dsp2 + 8704;
    unsigned* uP = dsp2 + 13056;
    float* srm  = (float*)(dsp2 + 17664);
    float* sinv = srm + 64;
    int t0 = blockIdx.x * 64, h = blockIdx.y, b = blockIdx.z;
    int tid = threadIdx.x, wid = tid >> 5, lane = tid & 31;
    int gr = lane >> 2, gc = lane & 3;
    const float* qb = g_q    + (size_t)b * S_ * D_ + h * DH_;
    const float* kb = g_k    + (size_t)b * S_ * D_ + h * DH_;
    const float* vb = g_vsel + (size_t)b * S_ * D_ + h * DH_;
    {
        int r = tid >> 2, dg = (tid & 3) * 16;
        const float* src = kb + (size_t)(t0 + r) * D_ + dg;
#pragma unroll
        for (int i = 0; i < 4; i++) {
            float4 v = *(const float4*)(src + i * 4);
            uK[(dg + i * 4 + 0) * 68 + r] = __float_as_uint(v.x);
            uK[(dg + i * 4 + 1) * 68 + r] = __float_as_uint(v.y);
            uK[(dg + i * 4 + 2) * 68 + r] = __float_as_uint(v.z);
            uK[(dg + i * 4 + 3) * 68 + r] = __float_as_uint(v.w);
        }
    }
    const int wm0 = (wid & 1) * 32, wn0 = (wid >> 1) * 16;
    float O[2][2][4];
#pragma unroll
    for (int mf = 0; mf < 2; mf++)
#pragma unroll
        for (int nf = 0; nf < 2; nf++)
#pragma unroll
            for (int q = 0; q < 4; q++) O[mf][nf][q] = 0.f;

    for (int st0 = t0; st0 < S_; st0 += 64) {
        {
            int r = tid >> 2, dg = (tid & 3) * 16;
            const float* qsrc = qb + (size_t)(st0 + r) * D_ + dg;
            const float* vsrc = vb + (size_t)(st0 + r) * D_ + dg;
#pragma unroll
            for (int i = 0; i < 4; i++) {
                float4 v = *(const float4*)(qsrc + i * 4);
                uQ[r * 68 + dg + i * 4 + 0] = __float_as_uint(v.x);
                uQ[r * 68 + dg + i * 4 + 1] = __float_as_uint(v.y);
                uQ[r * 68 + dg + i * 4 + 2] = __float_as_uint(v.z);
                uQ[r * 68 + dg + i * 4 + 3] = __float_as_uint(v.w);
                float4 w = *(const float4*)(vsrc + i * 4);
                uV[r * 68 + dg + i * 4 + 0] = __float_as_uint(w.x);
                uV[r * 68 + dg + i * 4 + 1] = __float_as_uint(w.y);
                uV[r * 68 + dg + i * 4 + 2] = __float_as_uint(w.z);
                uV[r * 68 + dg + i * 4 + 3] = __float_as_uint(w.w);
            }
        }
        if (tid < 64) {
            int o = (b * H_ + h) * S_ + st0 + tid;
            srm[tid] = g_m[o]; sinv[tid] = 1.f / g_l[o];
        }
        __syncthreads();
        float c[2][2][4];
#pragma unroll
        for (int mf = 0; mf < 2; mf++)
#pragma unroll
            for (int nf = 0; nf < 2; nf++)
#pragma unroll
                for (int q = 0; q < 4; q++) c[mf][nf][q] = 0.f;
#pragma unroll
        for (int kk = 0; kk < 64; kk += 8) {
            unsigned a[2][4], bf[2][2];
#pragma unroll
            for (int mf = 0; mf < 2; mf++) {
                int mb = wm0 + mf * 16;
                a[mf][0] = uQ[(mb + gr)     * 68 + kk + gc];
                a[mf][1] = uQ[(mb + gr + 8) * 68 + kk + gc];
                a[mf][2] = uQ[(mb + gr)     * 68 + kk + gc + 4];
                a[mf][3] = uQ[(mb + gr + 8) * 68 + kk + gc + 4];
            }
#pragma unroll
            for (int nf = 0; nf < 2; nf++) {
                int nb = wn0 + nf * 8 + gr;
                bf[nf][0] = uK[(kk + gc)     * 68 + nb];
                bf[nf][1] = uK[(kk + gc + 4) * 68 + nb];
            }
#pragma unroll
            for (int mf = 0; mf < 2; mf++)
#pragma unroll
                for (int nf = 0; nf < 2; nf++)
                    mma_tf32(c[mf][nf], a[mf], bf[nf]);
        }
#pragma unroll
        for (int mf = 0; mf < 2; mf++) {
            int sl_a = wm0 + mf * 16 + gr;
            int sl_b = sl_a + 8;
            int gs_a = st0 + sl_a, gs_b = st0 + sl_b;
            float ma = srm[sl_a], ia = sinv[sl_a];
            float mb2 = srm[sl_b], ib = sinv[sl_b];
#pragma unroll
            for (int nf = 0; nf < 2; nf++) {
                int tc = wn0 + nf * 8 + 2 * gc;
                int gt0 = t0 + tc, gt1 = gt0 + 1;
                float p;
                p = (gt0 <= gs_a) ? __expf(c[mf][nf][0] * 0.125f - ma) * ia : 0.f;
                uP[tc * 72 + sl_a] = to_tf32(p);
                p = (gt1 <= gs_a) ? __expf(c[mf][nf][1] * 0.125f - ma) * ia : 0.f;
                uP[(tc + 1) * 72 + sl_a] = to_tf32(p);
                p = (gt0 <= gs_b) ? __expf(c[mf][nf][2] * 0.125f - mb2) * ib : 0.f;
                uP[tc * 72 + sl_b] = to_tf32(p);
                p = (gt1 <= gs_b) ? __expf(c[mf][nf][3] * 0.125f - mb2) * ib : 0.f;
                uP[(tc + 1) * 72 + sl_b] = to_tf32(p);
            }
        }
        __syncthreads();
#pragma unroll
        for (int kk = 0; kk < 64; kk += 8) {
            unsigned a[2][4], bf[2][2];
#pragma unroll
            for (int mf = 0; mf < 2; mf++) {
                int mb = wm0 + mf * 16;
                a[mf][0] = uP[(mb + gr)     * 72 + kk + gc];
                a[mf][1] = uP[(mb + gr + 8) * 72 + kk + gc];
                a[mf][2] = uP[(mb + gr)     * 72 + kk + gc + 4];
                a[mf][3] = uP[(mb + gr + 8) * 72 + kk + gc + 4];
            }
#pragma unroll
            for (int nf = 0; nf < 2; nf++) {
                int nb = wn0 + nf * 8 + gr;
                bf[nf][0] = uV[(kk + gc)     * 68 + nb];
                bf[nf][1] = uV[(kk + gc + 4) * 68 + nb];
            }
#pragma unroll
            for (int mf = 0; mf < 2; mf++)
#pragma unroll
                for (int nf = 0; nf < 2; nf++)
                    mma_tf32(O[mf][nf], a[mf], bf[nf]);
        }
        __syncthreads();
    }
#pragma unroll
    for (int mf = 0; mf < 2; mf++) {
        int trow = t0 + wm0 + mf * 16 + gr;
#pragma unroll
        for (int nf = 0; nf < 2; nf++) {
            int fc = wn0 + nf * 8 + 2 * gc;
            *(float2*)(g_attn + (size_t)(b * S_ + trow) * D_ + h * DH_ + fc)
                = make_float2(O[mf][nf][0], O[mf][nf][1]);
            *(float2*)(g_attn + (size_t)(b * S_ + trow + 8) * D_ + h * DH_ + fc)
                = make_float2(O[mf][nf][2], O[mf][nf][3]);
        }
    }
}

// ---------------- capacity + deterministic slot assignment (smem staged) -------
__global__ void capacity_kernel() {
    __shared__ int sidx[NTOK * 2];   // 32 KB
    int tid = threadIdx.x;
    for (int i = tid; i < NTOK * 2; i += 256) sidx[i] = g_tk_idx[i];
    __syncthreads();
    int w = tid >> 5, lane = tid & 31;
    if (w < E_) {
        int e = w, c = 0;
        for (int i0 = 0; i0 < NTOK * 2; i0 += 32) {
            int i = i0 + lane;
            int idx = sidx[i];
            bool match = (idx == e);
            unsigned msk = __ballot_sync(0xffffffffu, match);
            if (match) {
                int rank = c + __popc(msk & ((1u << lane) - 1u));
                if (rank < CAP_) {
                    g_slot_token[e * CAP_ + rank] = i >> 1;
                    g_token_slot[i] = e * CAP_ + rank;
                } else {
                    g_token_slot[i] = -1;
                }
            }
            c += __popc(msk);
        }
        if (lane == 0) g_ecount[e] = (c < CAP_) ? c : CAP_;
    }
    __syncthreads();
    for (int t = tid; t < NTOK; t += 256) {
        int s0 = g_token_slot[2 * t], s1 = g_token_slot[2 * t + 1];
        float p0 = (s0 >= 0) ? g_tk_prob[2 * t]     : 0.f;
        float p1 = (s1 >= 0) ? g_tk_prob[2 * t + 1] : 0.f;
        float inv = 1.f / (p0 + p1 + 1e-9f);
        if (s0 >= 0) g_slot_w[s0] = p0 * inv;
        if (s1 >= 0) g_slot_w[s1] = p1 * inv;
    }
}

// ---------------- combine: out = x1 + f (warp per row, float4) -----------------
__global__ void combine_kernel(float* __restrict__ out) {
    int wid = threadIdx.x >> 5, lane = threadIdx.x & 31;
    int row = blockIdx.x * 8 + wid;
    int s0 = g_token_slot[2 * row], s1 = g_token_slot[2 * row + 1];
    const float4* xr = (const float4*)(g_x1 + (size_t)row * D_);
    const float4* f0 = (s0 >= 0) ? (const float4*)(g_sout + (size_t)s0 * D_) : nullptr;
    const float4* f1 = (s1 >= 0) ? (const float4*)(g_sout + (size_t)s1 * D_) : nullptr;
    float4* orow = (float4*)(out + (size_t)row * D_);
#pragma unroll
    for (int i = 0; i < 6; i++) {
        int c = lane + i * 32;
        float4 v = xr[c];
        if (f0) { float4 a = f0[c]; v.x += a.x; v.y += a.y; v.z += a.z; v.w += a.w; }
        if (f1) { float4 a = f1[c]; v.x += a.x; v.y += a.y; v.z += a.z; v.w += a.w; }
        orow[c] = v;
    }
}

// ---------------- aux losses (parallelized) ------------------------------------
__global__ void aux_kernel(float* __restrict__ out, int out_size) {
    __shared__ float ic_sh[E_];
    __shared__ float sa;
    int tid = threadIdx.x, w = tid >> 5, lane = tid & 31;
    if (w < E_) {
        int c = g_ecount[w];
        float s = 0.f;
        for (int r = lane; r < c; r += 32) s += g_slot_w[w * CAP_ + r];
#pragma unroll
        for (int o = 16; o > 0; o >>= 1) s += __shfl_down_sync(0xffffffffu, s, o);
        if (lane == 0) ic_sh[w] = s;
    }
    __syncthreads();
    if (tid == 0) {
        const float scale = 0.01f / 2048.f;
        float es = 0.f;
        for (int i = 0; i < H_ * E_; i++) es += g_hcnt[i] * scale;
        float a1 = 0.f;
        for (int i = 0; i < H_ * E_; i++) {
            float p = (g_hcnt[i] * scale) / (es + 1e-9f);
            a1 += p * p;
        }
        a1 *= (float)(E_ * H_);
        float tcs = 0.f, ics = 0.f;
        for (int e = 0; e < E_; e++) { tcs += (float)g_ecount[e]; ics += ic_sh[e]; }
        float a2 = 0.f;
        for (int e = 0; e < E_; e++) a2 += ((float)g_ecount[e] / tcs) * (ic_sh[e] / ics);
        a2 *= (float)E_;
        sa = a1 + a2;
    }
    __syncthreads();
    for (int i = NOUT + tid; i < out_size; i += blockDim.x) out[i] = sa;
}

// ---------------- launch -------------------------------------------------------
extern "C" void kernel_launch(void* const* d_in, const int* in_sizes, int n_in,
                              void* d_out, int out_size) {
    const float* x   = (const float*)d_in[0];
    // d_in[1] = mask (pure causal 0/-1e9, applied analytically)
    const float* Wq  = (const float*)d_in[2];
    const float* Wk  = (const float*)d_in[3];
    const float* Wv  = (const float*)d_in[4];
    const float* Wo  = (const float*)d_in[5];
    const float* Wr  = (const float*)d_in[6];
    const float* g1  = (const float*)d_in[7];
    const float* b1  = (const float*)d_in[8];
    const float* g2  = (const float*)d_in[9];
    const float* b2  = (const float*)d_in[10];
    const float* gff = (const float*)d_in[11];
    const float* W1  = (const float*)d_in[12];
    const float* W2  = (const float*)d_in[13];
    float* out = (float*)d_out;

    float *p_xln, *p_x1, *p_xln2;
    cudaGetSymbolAddress((void**)&p_xln,  g_xln);
    cudaGetSymbolAddress((void**)&p_x1,   g_x1);
    cudaGetSymbolAddress((void**)&p_xln2, g_xln2);

    const int pass1_smem = (2 * 64 * 68 + 64 * 72) * 4;
    const int pass2_smem = (3 * 64 * 68 + 64 * 72 + 128) * 4;
    cudaFuncSetAttribute(attn_pass1, cudaFuncAttributeMaxDynamicSharedMemorySize, pass1_smem);
    cudaFuncSetAttribute(attn_pass2, cudaFuncAttributeMaxDynamicSharedMemorySize, pass2_smem);

    ln_kernel<<<NTOK / 8, 256>>>(x, g1, b1, p_xln, 1);
    gemm_tf32<0><<<dim3(26, NTOK / 128, 1), 256>>>(Wq, Wk, Wr);   // Q, K, router fused
    router_argmax<<<(NTOK * H_ + 255) / 256, 256>>>();
    sel_gemm<0><<<dim3(H_ * E_, NTOK / 64), 256>>>(Wv, nullptr);
    attn_pass1<<<dim3(S_ / 64, H_, B_), 256, pass1_smem>>>();
    attn_pass2<<<dim3(S_ / 64, H_, B_), 256, pass2_smem>>>();
    sel_gemm<1><<<dim3(H_ * E_, NTOK / 64), 256>>>(Wo, x);
    ln_gate_kernel<<<NTOK / 8, 256>>>(p_x1, g2, b2, gff, p_xln2);
    capacity_kernel<<<1, 256>>>();
    gemm_tf32<1><<<dim3(DFF_ / 64, (CAP_ + 127) / 128, E_), 256>>>(W1, nullptr, nullptr);
    gemm_tf32<2><<<dim3(D_ / 64, (CAP_ + 127) / 128, E_), 256>>>(W2, nullptr, nullptr);
    combine_kernel<<<NTOK / 8, 256>>>(out);
    if (out_size > NOUT) aux_kernel<<<1, 256>>>(out, out_size);
}